// round 1
// baseline (speedup 1.0000x reference)
#include <cuda_runtime.h>
#include <math.h>

// ----------------------------------------------------------------------------
// Problem constants
//   query_map: (8, 256, 64, 64)   kv_map: (8, 256, 32, 32)
//   q_w/k_w/v_w/out_w: (256,256)  offset_w: (64,256,3,3)  offset_b: (64)
//   heads H=8, points P=4, D=32
//   output: (8, 256, 64, 64) float32
// ----------------------------------------------------------------------------

#define NB      8
#define NC      256
#define NHEAD   8
#define NPOINT  4
#define DDIM    32
#define HQ      64
#define WQ      64
#define PIXQ    4096
#define HKV     32
#define WKV     32
#define PIXK    1024

// Scratch (device globals; allocation-free rule)
__device__ float g_q[64 * 4096 * 32];      // (n=b*H, pix, d)
__device__ float g_k[64 * 1024 * 32];      // (n, pix_k, d)
__device__ float g_v[64 * 1024 * 32];
__device__ float g_grids[64 * 4 * 4096 * 2]; // (n, p, pix, {x,y})
__device__ float g_attn[8 * 4096 * 256];   // (b, pix, c)

enum { MODE_PROJ = 0, MODE_OUT = 1, MODE_CONV = 2 };

// ----------------------------------------------------------------------------
// One templated tiled SGEMM used in three modes:
//  MODE_PROJ: out(M=256, N=pix) = W(256x256) * X(b)(256 x Npix)   (NN)
//             epilogue -> head-transposed scratch (n, pix, d)
//  MODE_CONV: 3x3 conv as implicit GEMM, M=64, K=2304 (k = tap*256 + c),
//             shifted/predicated B loads; epilogue: +bias, tanh*0.25 + base
//             grid -> g_grids
//  MODE_OUT : out(M=256, N=pix) = out_w(256x256) * attn(b)(pix x 256)^T (NT)
//             epilogue -> d_out (b, m, pix)
// ----------------------------------------------------------------------------
template <int MODE, int BM, int BN, int BK, int TM, int TN>
__global__ __launch_bounds__(256) void gemm_kernel(
    const float* __restrict__ A,     // weights
    const float* __restrict__ Bmat,  // input (PROJ/CONV); unused for OUT
    const float* __restrict__ bias,  // CONV only
    float* __restrict__ dst,         // OUT only (d_out)
    int K, int Npix, int which)      // which: 0=q, 1=k, 2=v (PROJ)
{
    const int t  = threadIdx.x;
    const int b  = blockIdx.z;
    const int n0 = blockIdx.x * BN;
    const int m0 = blockIdx.y * BM;

    __shared__ __align__(16) float As[BK][BM];
    __shared__ __align__(16) float Bs[BK][BN];

    // BN/TN == 16 in all instantiations
    const int tn_idx = t & 15;
    const int tm_idx = t >> 4;
    const int mBase  = tm_idx * TM;
    const int nBase  = tn_idx * TN;

    float acc[TM][TN];
#pragma unroll
    for (int i = 0; i < TM; i++)
#pragma unroll
        for (int j = 0; j < TN; j++) acc[i][j] = 0.f;

    const float* Bb;
    if (MODE == MODE_PROJ)      Bb = Bmat + (size_t)b * 256 * Npix;
    else if (MODE == MODE_CONV) Bb = Bmat + (size_t)b * 256 * 4096;
    else                        Bb = g_attn + (size_t)b * 4096 * 256;

    for (int k0 = 0; k0 < K; k0 += BK) {
        // ---------------- load A tile -> As[k][m] ----------------
        if (MODE != MODE_CONV) {
            // A row-major (M, K=256), BM=128, BK=16: 2048 elems / 256 thr = 8
            int ar = t >> 1;
            int ac = (t & 1) * 8;
            const float* Ap = A + (size_t)(m0 + ar) * K + k0 + ac;
            float4 a0 = *(const float4*)Ap;
            float4 a1 = *(const float4*)(Ap + 4);
            As[ac + 0][ar] = a0.x; As[ac + 1][ar] = a0.y;
            As[ac + 2][ar] = a0.z; As[ac + 3][ar] = a0.w;
            As[ac + 4][ar] = a1.x; As[ac + 5][ar] = a1.y;
            As[ac + 6][ar] = a1.z; As[ac + 7][ar] = a1.w;
        } else {
            // offset_w (64, 256, 3, 3); k = tap*256 + c
            int ar  = t >> 2;          // 0..63 (= oc, m0 == 0)
            int ac2 = (t & 3) * 2;     // 0,2,4,6
            int tap = k0 >> 8;
            int cb  = (k0 & 255) + ac2;
            As[ac2 + 0][ar] = A[(size_t)ar * 2304 + (cb + 0) * 9 + tap];
            As[ac2 + 1][ar] = A[(size_t)ar * 2304 + (cb + 1) * 9 + tap];
        }
        // ---------------- load B tile -> Bs[k][n] ----------------
        if (MODE == MODE_PROJ) {
            // X (256, Npix), row (pixels) contiguous. BK=16, BN=64.
            int bkk = t >> 4;
            int bn  = (t & 15) * 4;
            *(float4*)&Bs[bkk][bn] =
                *(const float4*)(Bb + (size_t)(k0 + bkk) * Npix + n0 + bn);
        } else if (MODE == MODE_OUT) {
            // attn (pix, c): B[n,k] contiguous in k. BK=16, BN=64.
            int bn  = t & 63;
            int bkq = (t >> 6) * 4;
            const float* Bp = Bb + (size_t)(n0 + bn) * 256 + k0 + bkq;
            float4 v = *(const float4*)Bp;
            Bs[bkq + 0][bn] = v.x; Bs[bkq + 1][bn] = v.y;
            Bs[bkq + 2][bn] = v.z; Bs[bkq + 3][bn] = v.w;
        } else {
            // shifted conv patch, zero padded. BK=8, BN=128.
            int bkk = t >> 5;            // 0..7
            int bn4 = (t & 31) * 4;
            int tap = k0 >> 8;
            int c   = (k0 & 255) + bkk;
            int dy  = tap / 3 - 1;
            int dx  = tap - (tap / 3) * 3 - 1;
            const float* Xc = Bb + (size_t)c * 4096;
            float4 v;
            float* vp = &v.x;
#pragma unroll
            for (int e = 0; e < 4; e++) {
                int pix = n0 + bn4 + e;
                int py = pix >> 6, px = pix & 63;
                int sy = py + dy, sx = px + dx;
                float val = 0.f;
                if ((unsigned)sy < 64u && (unsigned)sx < 64u)
                    val = Xc[sy * 64 + sx];
                vp[e] = val;
            }
            *(float4*)&Bs[bkk][bn4] = v;
        }
        __syncthreads();

        // ---------------- compute ----------------
#pragma unroll
        for (int kk = 0; kk < BK; kk++) {
            float a[TM], bb[TN];
#pragma unroll
            for (int i = 0; i < TM; i += 4)
                *(float4*)&a[i] = *(const float4*)&As[kk][mBase + i];
#pragma unroll
            for (int j = 0; j < TN; j += 4)
                *(float4*)&bb[j] = *(const float4*)&Bs[kk][nBase + j];
#pragma unroll
            for (int i = 0; i < TM; i++)
#pragma unroll
                for (int j = 0; j < TN; j++)
                    acc[i][j] = fmaf(a[i], bb[j], acc[i][j]);
        }
        __syncthreads();
    }

    // ---------------- epilogues ----------------
    if (MODE == MODE_PROJ) {
        float* dstp = (which == 0) ? g_q : ((which == 1) ? g_k : g_v);
#pragma unroll
        for (int i = 0; i < TM; i++) {
            int m  = m0 + mBase + i;         // 0..255
            int hh = m >> 5, d = m & 31;
            float* o = dstp + ((size_t)(b * 8 + hh) * Npix) * 32 + d;
#pragma unroll
            for (int j = 0; j < TN; j++) {
                int pix = n0 + nBase + j;
                o[(size_t)pix * 32] = acc[i][j];
            }
        }
    } else if (MODE == MODE_OUT) {
#pragma unroll
        for (int i = 0; i < TM; i++) {
            int m = m0 + mBase + i;
            float* o = dst + (size_t)b * (256 * 4096) + (size_t)m * 4096 + n0 + nBase;
            float4 v;
            v.x = acc[i][0]; v.y = acc[i][1]; v.z = acc[i][2]; v.w = acc[i][3];
            *(float4*)o = v;
        }
    } else {  // MODE_CONV -> grids
#pragma unroll
        for (int i = 0; i < TM; i++) {
            int m    = mBase + i;            // 0..63
            int hh   = m >> 3;
            int p    = (m >> 1) & 3;
            int comp = m & 1;
            float bv = bias[m];
#pragma unroll
            for (int j = 0; j < TN; j++) {
                int pix = n0 + nBase + j;
                int py = pix >> 6, px = pix & 63;
                float base = comp ? (py * (2.f / 63.f) - 1.f)
                                  : (px * (2.f / 63.f) - 1.f);
                float v = tanhf(acc[i][j] + bv) * 0.25f + base;
                g_grids[((((size_t)(b * 8 + hh) * 4 + p) * 4096) + pix) * 2 + comp] = v;
            }
        }
    }
}

// ----------------------------------------------------------------------------
// Fused bilinear sampling + attention.
// One warp per (n = b*H + head, pixel); lane = d channel (D=32).
// k/v stored (n, pix_k, d) so each tap load is one coalesced 128B line.
// ----------------------------------------------------------------------------
__global__ __launch_bounds__(256) void attn_kernel()
{
    int gw   = blockIdx.x * 8 + (threadIdx.x >> 5);
    int lane = threadIdx.x & 31;
    int n    = gw >> 12;           // 0..63
    int pix  = gw & 4095;
    int b    = n >> 3;
    int hh   = n & 7;

    float qv = g_q[((size_t)n * 4096 + pix) * 32 + lane];
    const float* kb = g_k + (size_t)n * 1024 * 32;
    const float* vb = g_v + (size_t)n * 1024 * 32;
    const float2* gp = (const float2*)g_grids + (size_t)n * 4 * 4096 + pix;

    float logit[4], vs[4];
#pragma unroll
    for (int p = 0; p < 4; p++) {
        float2 g = gp[(size_t)p * 4096];
        float x = (g.x + 1.f) * 16.f - 0.5f;
        float y = (g.y + 1.f) * 16.f - 0.5f;
        float x0f = floorf(x), y0f = floorf(y);
        float wx1 = x - x0f, wy1 = y - y0f;
        int x0 = (int)x0f, y0 = (int)y0f;
        float ks = 0.f, vv = 0.f;
#pragma unroll
        for (int dy = 0; dy < 2; dy++) {
#pragma unroll
            for (int dx = 0; dx < 2; dx++) {
                int xi = x0 + dx, yi = y0 + dy;
                float w = (dx ? wx1 : 1.f - wx1) * (dy ? wy1 : 1.f - wy1);
                if ((unsigned)xi < 32u && (unsigned)yi < 32u) {
                    int off = ((yi << 5) + xi) << 5;  // *32
                    ks = fmaf(w, kb[off + lane], ks);
                    vv = fmaf(w, vb[off + lane], vv);
                }
            }
        }
        float tsum = qv * ks;
#pragma unroll
        for (int o = 16; o > 0; o >>= 1)
            tsum += __shfl_xor_sync(0xffffffffu, tsum, o);
        logit[p] = tsum * 0.17677669529663687f;  // 1/sqrt(32)
        vs[p] = vv;
    }

    float mx = fmaxf(fmaxf(logit[0], logit[1]), fmaxf(logit[2], logit[3]));
    float e0 = expf(logit[0] - mx);
    float e1 = expf(logit[1] - mx);
    float e2 = expf(logit[2] - mx);
    float e3 = expf(logit[3] - mx);
    float inv = 1.f / (e0 + e1 + e2 + e3);
    float o = (e0 * vs[0] + e1 * vs[1] + e2 * vs[2] + e3 * vs[3]) * inv;

    g_attn[((size_t)b * 4096 + pix) * 256 + hh * 32 + lane] = o;
}

// ----------------------------------------------------------------------------
extern "C" void kernel_launch(void* const* d_in, const int* in_sizes, int n_in,
                              void* d_out, int out_size)
{
    (void)in_sizes; (void)n_in; (void)out_size;
    const float* query = (const float*)d_in[0];
    const float* kv    = (const float*)d_in[1];
    const float* q_w   = (const float*)d_in[2];
    const float* k_w   = (const float*)d_in[3];
    const float* v_w   = (const float*)d_in[4];
    const float* off_w = (const float*)d_in[5];
    const float* off_b = (const float*)d_in[6];
    const float* out_w = (const float*)d_in[7];
    float* out = (float*)d_out;

    // q projection: (256 x 256) @ (256 x 4096) per batch -> g_q (n,pix,d)
    gemm_kernel<MODE_PROJ, 128, 64, 16, 8, 4>
        <<<dim3(4096 / 64, 256 / 128, 8), 256>>>(q_w, query, nullptr, nullptr,
                                                 256, 4096, 0);
    // k / v projections: (256 x 256) @ (256 x 1024) per batch
    gemm_kernel<MODE_PROJ, 128, 64, 16, 8, 4>
        <<<dim3(1024 / 64, 256 / 128, 8), 256>>>(k_w, kv, nullptr, nullptr,
                                                 256, 1024, 1);
    gemm_kernel<MODE_PROJ, 128, 64, 16, 8, 4>
        <<<dim3(1024 / 64, 256 / 128, 8), 256>>>(v_w, kv, nullptr, nullptr,
                                                 256, 1024, 2);
    // offset conv3x3 + tanh + base grid -> g_grids
    gemm_kernel<MODE_CONV, 64, 128, 8, 4, 8>
        <<<dim3(4096 / 128, 1, 8), 256>>>(off_w, query, off_b, nullptr,
                                          2304, 4096, 0);
    // fused bilinear sample + attention -> g_attn
    attn_kernel<<<(64 * 4096) / 8, 256>>>();
    // output projection (NT) -> d_out
    gemm_kernel<MODE_OUT, 128, 64, 16, 8, 4>
        <<<dim3(4096 / 64, 256 / 128, 8), 256>>>(out_w, nullptr, nullptr, out,
                                                 256, 4096, 0);
}

// round 4
// speedup vs baseline: 1.9502x; 1.9502x over previous
#include <cuda_runtime.h>
#include <cuda_bf16.h>
#include <math.h>
#include <stdint.h>

// ----------------------------------------------------------------------------
// DeformableCrossAttention2D on plain sm_100: split-bf16 mma.sync everywhere.
//   query_map: (8, 256, 64, 64)   kv_map: (8, 256, 32, 32)
//   q_w/k_w/v_w/out_w: (256,256)  offset_w: (64,256,3,3)  offset_b: (64)
//   heads H=8, points P=4, D=32;  output: (8, 256, 64, 64) float32
// ----------------------------------------------------------------------------

// ---------------- scratch (device globals; allocation-free rule) -------------
__device__ float g_q[64 * 4096 * 32];        // (n=b*H, pix, d)
__device__ float g_k[64 * 1024 * 32];        // (n, pix_k, d)
__device__ float g_v[64 * 1024 * 32];
__device__ float g_grids[64 * 4 * 4096 * 2]; // (n, p, pix, {x,y})

__device__ uint32_t g_qimg[8 * 256 * 66 * 66];  // padded image, (bf16hi<<16)|bf16lo
__device__ __align__(16) uint16_t g_wch[9 * 64 * 256];   // conv weights [tap][oc][c] hi
__device__ __align__(16) uint16_t g_wcl[9 * 64 * 256];   // lo
__device__ __align__(16) uint16_t g_pwh[4 * 256 * 256];  // proj/out weights [slot][m][k] hi
__device__ __align__(16) uint16_t g_pwl[4 * 256 * 256];  // lo
__device__ __align__(16) uint16_t g_xqh[8 * 4096 * 256]; // query^T [b][pix][c] hi
__device__ __align__(16) uint16_t g_xql[8 * 4096 * 256];
__device__ __align__(16) uint16_t g_xkh[8 * 1024 * 256]; // kv^T
__device__ __align__(16) uint16_t g_xkl[8 * 1024 * 256];
__device__ __align__(16) uint16_t g_attnh[8 * 4096 * 256]; // attn out [b][pix][c]
__device__ __align__(16) uint16_t g_attnl[8 * 4096 * 256];

// ---------------- helpers ----------------------------------------------------
__device__ __forceinline__ void split_bf16(float v, uint16_t& h, uint16_t& l) {
    __nv_bfloat16 hb = __float2bfloat16(v);
    float r = v - __bfloat162float(hb);
    h = __bfloat16_as_ushort(hb);
    l = __bfloat16_as_ushort(__float2bfloat16(r));
}

__device__ __forceinline__ void mma_bf16(float* c, const uint32_t* a, const uint32_t* b) {
    asm volatile(
        "mma.sync.aligned.m16n8k16.row.col.f32.bf16.bf16.f32 "
        "{%0,%1,%2,%3}, {%4,%5,%6,%7}, {%8,%9}, {%0,%1,%2,%3};"
        : "+f"(c[0]), "+f"(c[1]), "+f"(c[2]), "+f"(c[3])
        : "r"(a[0]), "r"(a[1]), "r"(a[2]), "r"(a[3]), "r"(b[0]), "r"(b[1]));
}

// ---------------- prep kernels -----------------------------------------------
// Pad query (8,256,64,64) -> g_qimg (8,256,66,66) as (bf16hi<<16)|bf16lo
__global__ __launch_bounds__(256) void prep_img_kernel(const float* __restrict__ q) {
    int idx = blockIdx.x * 256 + threadIdx.x;
    if (idx >= 8 * 256 * 66 * 66) return;
    int bc  = idx / 4356;
    int rem = idx - bc * 4356;
    int y = rem / 66, x = rem - y * 66;
    float v = 0.f;
    if (y >= 1 && y <= 64 && x >= 1 && x <= 64)
        v = q[(size_t)bc * 4096 + (y - 1) * 64 + (x - 1)];
    uint16_t h, l;
    split_bf16(v, h, l);
    g_qimg[idx] = ((uint32_t)h << 16) | (uint32_t)l;
}

// offset_w (64,256,3,3) -> g_wch/g_wcl [tap][oc][c]
__global__ __launch_bounds__(256) void prep_w_kernel(const float* __restrict__ w) {
    int idx = blockIdx.x * 256 + threadIdx.x;
    if (idx >= 9 * 64 * 256) return;
    int tap = idx >> 14;
    int rem = idx & 16383;
    int oc = rem >> 8, c = rem & 255;
    uint16_t h, l;
    split_bf16(w[(size_t)oc * 2304 + c * 9 + tap], h, l);
    g_wch[idx] = h;
    g_wcl[idx] = l;
}

// Split a (256,256) fp32 weight matrix into hi/lo bf16 at slot.
__global__ __launch_bounds__(256) void prep_pw_kernel(const float* __restrict__ w, int slot) {
    int idx = blockIdx.x * 256 + threadIdx.x;   // 0..65535
    uint16_t h, l;
    split_bf16(w[idx], h, l);
    g_pwh[(size_t)slot * 65536 + idx] = h;
    g_pwl[(size_t)slot * 65536 + idx] = l;
}

// Transpose+split: x (B,256,Npix) fp32 -> oh/ol [b][pix][c] bf16
__global__ __launch_bounds__(256) void tsplit_kernel(
    const float* __restrict__ x, uint16_t* __restrict__ oh,
    uint16_t* __restrict__ ol, int Npix)
{
    __shared__ float tile[32][33];
    int p0 = blockIdx.x * 32, c0 = blockIdx.y * 32, b = blockIdx.z;
    int tx = threadIdx.x & 31, ty = threadIdx.x >> 5;
    const float* src = x + ((size_t)b * 256 + c0) * Npix + p0;
#pragma unroll
    for (int lquad = 0; lquad < 4; lquad++) {
        int cc = ty + lquad * 8;
        tile[cc][tx] = src[(size_t)cc * Npix + tx];
    }
    __syncthreads();
#pragma unroll
    for (int lquad = 0; lquad < 4; lquad++) {
        int pp = ty + lquad * 8;
        uint16_t h, l;
        split_bf16(tile[tx][pp], h, l);
        size_t o = ((size_t)b * Npix + p0 + pp) * 256 + c0 + tx;
        oh[o] = h;
        ol[o] = l;
    }
}

// ---------------- unified split-bf16 mma GEMM --------------------------------
// MODE_PROJ: C[m=oc 256][n=pix] = W * X^T-split      -> g_q/g_k/g_v (n,pix,d)
// MODE_OUT : C[m=oc 256][n=pix] = out_w * attn-split -> d_out
// MODE_CONV: C[m=pix 4096][n=oc 64], K=2304 implicit conv -> tanh/grid epilogue
enum { MODE_PROJ = 0, MODE_OUT = 1, MODE_CONV = 2 };

#define ASTR 40   // bf16 stride (32 + 8 pad)
#define BSTR 40

template <int MODE>
__global__ __launch_bounds__(256) void mma_gemm(
    const uint16_t* __restrict__ Ahg,   // pre-split W [m][k] (PROJ/OUT)
    const uint16_t* __restrict__ Alg,
    const uint16_t* __restrict__ Bhg,   // pre-split B, [b][n][k] (PROJ/OUT)
    const uint16_t* __restrict__ Blg,
    const float* __restrict__ bias,     // CONV
    float* __restrict__ dst,            // OUT
    int Npix, int which)
{
    __shared__ __align__(16) uint16_t Ah[128 * ASTR];
    __shared__ __align__(16) uint16_t Al[128 * ASTR];
    __shared__ __align__(16) uint16_t Bh[64 * BSTR];
    __shared__ __align__(16) uint16_t Bl[64 * BSTR];

    const int t = threadIdx.x;
    const int lane = t & 31, wid = t >> 5;
    const int warp_m = wid & 3;       // 4 tiles of 32 in M=128
    const int warp_n = wid >> 2;      // 2 tiles of 32 in N=64
    const int bb = blockIdx.z;

    int m0, n0;
    if (MODE == MODE_CONV) { m0 = blockIdx.x * 128; n0 = 0; }
    else                   { n0 = blockIdx.x * 64;  m0 = blockIdx.y * 128; }

    float c[2][4][4];
#pragma unroll
    for (int i = 0; i < 2; i++)
#pragma unroll
        for (int j = 0; j < 4; j++)
#pragma unroll
            for (int r = 0; r < 4; r++) c[i][j][r] = 0.f;

    const int nkb = (MODE == MODE_CONV) ? 72 : 8;

    for (int kb = 0; kb < nkb; kb++) {
        if (kb) __syncthreads();
        // ---------------- stage A ----------------
        if (MODE != MODE_CONV) {
            int m = t >> 1, half = (t & 1) * 16;
            size_t off = (size_t)(m0 + m) * 256 + kb * 32 + half;
            uint32_t* dh = (uint32_t*)Ah + m * 20 + (half >> 1);
            uint32_t* dl = (uint32_t*)Al + m * 20 + (half >> 1);
            *(uint4*)(dh)     = *(const uint4*)(Ahg + off);
            *(uint4*)(dh + 4) = *(const uint4*)(Ahg + off + 8);
            *(uint4*)(dl)     = *(const uint4*)(Alg + off);
            *(uint4*)(dl + 4) = *(const uint4*)(Alg + off + 8);
        } else {
            int r = t >> 1, half = (t & 1) * 16;
            int tap = kb >> 3, c0 = (kb & 7) * 32;
            int dy = tap / 3 - 1, dx = tap - (tap / 3) * 3 - 1;
            int py = (m0 >> 6) + (r >> 6);
            int px = r & 63;
            const uint32_t* src = g_qimg +
                ((size_t)(bb * 256 + c0 + half) * 66 + (py + dy + 1)) * 66 + (px + dx + 1);
            uint32_t* dh = (uint32_t*)Ah + r * 20 + (half >> 1);
            uint32_t* dl = (uint32_t*)Al + r * 20 + (half >> 1);
#pragma unroll
            for (int j = 0; j < 8; j++) {
                uint32_t u0 = src[(size_t)(2 * j) * 4356];
                uint32_t u1 = src[(size_t)(2 * j + 1) * 4356];
                dh[j] = (u0 >> 16) | (u1 & 0xFFFF0000u);
                dl[j] = (u0 & 0xFFFFu) | (u1 << 16);
            }
        }
        // ---------------- stage B ----------------
        if (MODE == MODE_CONV) {
            int oc = t >> 2, q = t & 3;
            int tap = kb >> 3, c0 = (kb & 7) * 32;
            size_t off = (size_t)(tap * 64 + oc) * 256 + c0 + q * 8;
            ((uint4*)&Bh[oc * BSTR])[q] = *(const uint4*)(g_wch + off);
            ((uint4*)&Bl[oc * BSTR])[q] = *(const uint4*)(g_wcl + off);
        } else {
            int n = t >> 2, q = t & 3;
            size_t off = ((size_t)bb * Npix + n0 + n) * 256 + kb * 32 + q * 8;
            ((uint4*)&Bh[n * BSTR])[q] = *(const uint4*)(Bhg + off);
            ((uint4*)&Bl[n * BSTR])[q] = *(const uint4*)(Blg + off);
        }
        __syncthreads();
        // ---------------- compute: 2 k16 steps x 3 precision passes ----------
        const uint32_t* A32h = (const uint32_t*)Ah;
        const uint32_t* A32l = (const uint32_t*)Al;
        const uint32_t* B32h = (const uint32_t*)Bh;
        const uint32_t* B32l = (const uint32_t*)Bl;
        const int ml = warp_m * 32 + (lane >> 2);
        const int nl = warp_n * 32 + (lane >> 2);
        const int kq = lane & 3;
#pragma unroll
        for (int ks = 0; ks < 2; ks++) {
            const int kk = ks * 8 + kq;  // u32 offset along k
            uint32_t ah[2][4], al[2][4], bh4[4][2], bl4[4][2];
#pragma unroll
            for (int i = 0; i < 2; i++) {
                int base = (ml + i * 16) * 20 + kk;
                ah[i][0] = A32h[base];
                ah[i][1] = A32h[base + 160];
                ah[i][2] = A32h[base + 4];
                ah[i][3] = A32h[base + 164];
            }
#pragma unroll
            for (int j = 0; j < 4; j++) {
                int base = (nl + j * 8) * 20 + kk;
                bh4[j][0] = B32h[base];
                bh4[j][1] = B32h[base + 4];
                bl4[j][0] = B32l[base];
                bl4[j][1] = B32l[base + 4];
            }
#pragma unroll
            for (int i = 0; i < 2; i++)
#pragma unroll
                for (int j = 0; j < 4; j++)
                    mma_bf16(c[i][j], ah[i], bh4[j]);
#pragma unroll
            for (int i = 0; i < 2; i++)
#pragma unroll
                for (int j = 0; j < 4; j++)
                    mma_bf16(c[i][j], ah[i], bl4[j]);
#pragma unroll
            for (int i = 0; i < 2; i++) {
                int base = (ml + i * 16) * 20 + kk;
                al[i][0] = A32l[base];
                al[i][1] = A32l[base + 160];
                al[i][2] = A32l[base + 4];
                al[i][3] = A32l[base + 164];
            }
#pragma unroll
            for (int i = 0; i < 2; i++)
#pragma unroll
                for (int j = 0; j < 4; j++)
                    mma_bf16(c[i][j], al[i], bh4[j]);
        }
    }

    // ---------------- epilogues ----------------
#pragma unroll
    for (int i = 0; i < 2; i++) {
#pragma unroll
        for (int j = 0; j < 4; j++) {
#pragma unroll
            for (int r = 0; r < 4; r++) {
                int mm = warp_m * 32 + i * 16 + (lane >> 2) + ((r & 2) ? 8 : 0);
                int nn = warp_n * 32 + j * 8 + (lane & 3) * 2 + (r & 1);
                float v = c[i][j][r];
                if (MODE == MODE_PROJ) {
                    int m = m0 + mm;           // oc
                    int n = n0 + nn;           // pix
                    int hh = m >> 5, d = m & 31;
                    float* dstp = (which == 0) ? g_q : ((which == 1) ? g_k : g_v);
                    dstp[((size_t)(bb * 8 + hh) * Npix + n) * 32 + d] = v;
                } else if (MODE == MODE_OUT) {
                    int m = m0 + mm;
                    int n = n0 + nn;
                    dst[((size_t)bb * 256 + m) * 4096 + n] = v;
                } else {  // CONV
                    int pix = m0 + mm;
                    int oc = nn;               // 0..63
                    float w = tanhf(v + __ldg(&bias[oc])) * 0.25f;
                    int comp = oc & 1;
                    int hh = oc >> 3, p = (oc >> 1) & 3;
                    int py = pix >> 6, px = pix & 63;
                    float base = comp ? (py * (2.f / 63.f) - 1.f)
                                      : (px * (2.f / 63.f) - 1.f);
                    g_grids[((((size_t)(bb * 8 + hh) * 4 + p) * 4096) + pix) * 2 + comp]
                        = w + base;
                }
            }
        }
    }
}

// ----------------------------------------------------------------------------
// Fused bilinear sampling + attention; emits split-bf16 for the OUT GEMM.
// ----------------------------------------------------------------------------
__global__ __launch_bounds__(256) void attn_kernel()
{
    int gw   = blockIdx.x * 8 + (threadIdx.x >> 5);
    int lane = threadIdx.x & 31;
    int n    = gw >> 12;
    int pix  = gw & 4095;
    int b    = n >> 3;
    int hh   = n & 7;

    float qv = g_q[((size_t)n * 4096 + pix) * 32 + lane];
    const float* kb = g_k + (size_t)n * 1024 * 32;
    const float* vb = g_v + (size_t)n * 1024 * 32;
    const float2* gp = (const float2*)g_grids + (size_t)n * 4 * 4096 + pix;

    float logit[4], vs[4];
#pragma unroll
    for (int p = 0; p < 4; p++) {
        float2 g = gp[(size_t)p * 4096];
        float x = (g.x + 1.f) * 16.f - 0.5f;
        float y = (g.y + 1.f) * 16.f - 0.5f;
        float x0f = floorf(x), y0f = floorf(y);
        float wx1 = x - x0f, wy1 = y - y0f;
        int x0 = (int)x0f, y0 = (int)y0f;
        float ks = 0.f, vv = 0.f;
#pragma unroll
        for (int dy = 0; dy < 2; dy++) {
#pragma unroll
            for (int dx = 0; dx < 2; dx++) {
                int xi = x0 + dx, yi = y0 + dy;
                float w = (dx ? wx1 : 1.f - wx1) * (dy ? wy1 : 1.f - wy1);
                if ((unsigned)xi < 32u && (unsigned)yi < 32u) {
                    int off = ((yi << 5) + xi) << 5;
                    ks = fmaf(w, kb[off + lane], ks);
                    vv = fmaf(w, vb[off + lane], vv);
                }
            }
        }
        float tsum = qv * ks;
#pragma unroll
        for (int o = 16; o > 0; o >>= 1)
            tsum += __shfl_xor_sync(0xffffffffu, tsum, o);
        logit[p] = tsum * 0.17677669529663687f;
        vs[p] = vv;
    }

    float mx = fmaxf(fmaxf(logit[0], logit[1]), fmaxf(logit[2], logit[3]));
    float e0 = expf(logit[0] - mx);
    float e1 = expf(logit[1] - mx);
    float e2 = expf(logit[2] - mx);
    float e3 = expf(logit[3] - mx);
    float inv = 1.f / (e0 + e1 + e2 + e3);
    float o = (e0 * vs[0] + e1 * vs[1] + e2 * vs[2] + e3 * vs[3]) * inv;

    uint16_t h, l;
    split_bf16(o, h, l);
    size_t idx = ((size_t)b * 4096 + pix) * 256 + hh * 32 + lane;
    g_attnh[idx] = h;
    g_attnl[idx] = l;
}

// ----------------------------------------------------------------------------
extern "C" void kernel_launch(void* const* d_in, const int* in_sizes, int n_in,
                              void* d_out, int out_size)
{
    (void)in_sizes; (void)n_in; (void)out_size;
    const float* query = (const float*)d_in[0];
    const float* kv    = (const float*)d_in[1];
    const float* q_w   = (const float*)d_in[2];
    const float* k_w   = (const float*)d_in[3];
    const float* v_w   = (const float*)d_in[4];
    const float* off_w = (const float*)d_in[5];
    const float* off_b = (const float*)d_in[6];
    const float* out_w = (const float*)d_in[7];
    float* out = (float*)d_out;

    // preps
    prep_img_kernel<<<(8 * 256 * 66 * 66 + 255) / 256, 256>>>(query);
    prep_w_kernel<<<(9 * 64 * 256 + 255) / 256, 256>>>(off_w);
    prep_pw_kernel<<<256, 256>>>(q_w, 0);
    prep_pw_kernel<<<256, 256>>>(k_w, 1);
    prep_pw_kernel<<<256, 256>>>(v_w, 2);
    prep_pw_kernel<<<256, 256>>>(out_w, 3);

    uint16_t *xqh, *xql, *xkh, *xkl, *ath, *atl, *pwh, *pwl;
    cudaGetSymbolAddress((void**)&xqh, g_xqh);
    cudaGetSymbolAddress((void**)&xql, g_xql);
    cudaGetSymbolAddress((void**)&xkh, g_xkh);
    cudaGetSymbolAddress((void**)&xkl, g_xkl);
    cudaGetSymbolAddress((void**)&ath, g_attnh);
    cudaGetSymbolAddress((void**)&atl, g_attnl);
    cudaGetSymbolAddress((void**)&pwh, g_pwh);
    cudaGetSymbolAddress((void**)&pwl, g_pwl);

    tsplit_kernel<<<dim3(4096 / 32, 8, 8), 256>>>(query, xqh, xql, 4096);
    tsplit_kernel<<<dim3(1024 / 32, 8, 8), 256>>>(kv, xkh, xkl, 1024);

    // projections
    mma_gemm<MODE_PROJ><<<dim3(64, 2, 8), 256>>>(
        pwh + 0 * 65536, pwl + 0 * 65536, xqh, xql, nullptr, nullptr, 4096, 0);
    mma_gemm<MODE_PROJ><<<dim3(16, 2, 8), 256>>>(
        pwh + 1 * 65536, pwl + 1 * 65536, xkh, xkl, nullptr, nullptr, 1024, 1);
    mma_gemm<MODE_PROJ><<<dim3(16, 2, 8), 256>>>(
        pwh + 2 * 65536, pwl + 2 * 65536, xkh, xkl, nullptr, nullptr, 1024, 2);

    // offset conv -> grids
    mma_gemm<MODE_CONV><<<dim3(32, 1, 8), 256>>>(
        nullptr, nullptr, nullptr, nullptr, off_b, nullptr, 4096, 0);

    // fused bilinear sample + attention -> split attn
    attn_kernel<<<(64 * 4096) / 8, 256>>>();

    // output projection -> d_out
    mma_gemm<MODE_OUT><<<dim3(64, 2, 8), 256>>>(
        pwh + 3 * 65536, pwl + 3 * 65536, ath, atl, nullptr, out, 4096, 0);
}

// round 5
// speedup vs baseline: 2.2667x; 1.1623x over previous
#include <cuda_runtime.h>
#include <cuda_bf16.h>
#include <math.h>
#include <stdint.h>

// ----------------------------------------------------------------------------
// DeformableCrossAttention2D, split-bf16 mma.sync (sm_100-safe).
//   query_map: (8, 256, 64, 64)   kv_map: (8, 256, 32, 32)
//   q_w/k_w/v_w/out_w: (256,256)  offset_w: (64,256,3,3)  offset_b: (64)
//   heads H=8, points P=4, D=32;  output: (8, 256, 64, 64) float32
// ----------------------------------------------------------------------------

// ---------------- scratch (device globals; allocation-free rule) -------------
__device__ float g_q[64 * 4096 * 32];        // (n=b*H, pix, d)
__device__ float g_k[64 * 1024 * 32];
__device__ float g_v[64 * 1024 * 32];
__device__ float g_grids[64 * 4 * 4096 * 2]; // (n, p, pix, {x,y})

// c-pair-interleaved padded image planes: [b][c2=128][y=66][x=68] u32
__device__ __align__(16) uint32_t g_i2h[8 * 128 * 66 * 68];
__device__ __align__(16) uint32_t g_i2l[8 * 128 * 66 * 68];
__device__ __align__(16) uint16_t g_wch[9 * 64 * 256];   // conv W [tap][oc][c] hi
__device__ __align__(16) uint16_t g_wcl[9 * 64 * 256];
__device__ __align__(16) uint16_t g_pwh[4 * 256 * 256];  // proj/out W [slot][m][k]
__device__ __align__(16) uint16_t g_pwl[4 * 256 * 256];
__device__ __align__(16) uint16_t g_xqh[8 * 4096 * 256]; // query^T [b][pix][c]
__device__ __align__(16) uint16_t g_xql[8 * 4096 * 256];
__device__ __align__(16) uint16_t g_xkh[8 * 1024 * 256]; // kv^T
__device__ __align__(16) uint16_t g_xkl[8 * 1024 * 256];
__device__ __align__(16) uint16_t g_attnh[8 * 4096 * 256];
__device__ __align__(16) uint16_t g_attnl[8 * 4096 * 256];

// ---------------- helpers ----------------------------------------------------
__device__ __forceinline__ void split_bf16(float v, uint16_t& h, uint16_t& l) {
    __nv_bfloat16 hb = __float2bfloat16(v);
    float r = v - __bfloat162float(hb);
    h = __bfloat16_as_ushort(hb);
    l = __bfloat16_as_ushort(__float2bfloat16(r));
}

__device__ __forceinline__ void mma_bf16(float* c, const uint32_t* a, const uint32_t* b) {
    asm volatile(
        "mma.sync.aligned.m16n8k16.row.col.f32.bf16.bf16.f32 "
        "{%0,%1,%2,%3}, {%4,%5,%6,%7}, {%8,%9}, {%0,%1,%2,%3};"
        : "+f"(c[0]), "+f"(c[1]), "+f"(c[2]), "+f"(c[3])
        : "r"(a[0]), "r"(a[1]), "r"(a[2]), "r"(a[3]), "r"(b[0]), "r"(b[1]));
}

__device__ __forceinline__ uint32_t smem_u32(const void* p) {
    uint32_t a;
    asm("{ .reg .u64 t; cvta.to.shared.u64 t, %1; cvt.u32.u64 %0, t; }" : "=r"(a) : "l"(p));
    return a;
}
#define CP16(dst, src) \
    asm volatile("cp.async.cg.shared.global [%0], [%1], 16;" :: "r"(dst), "l"(src) : "memory")
#define CP_COMMIT() asm volatile("cp.async.commit_group;" ::: "memory")
#define CP_WAIT0()  asm volatile("cp.async.wait_group 0;" ::: "memory")

// ---------------- prep kernels -----------------------------------------------
// query (8,256,64,64) -> c-pair interleaved padded planes (hi/lo)
__global__ __launch_bounds__(256) void prep_img2_kernel(const float* __restrict__ q) {
    int idx = blockIdx.x * 256 + threadIdx.x;
    if (idx >= 8 * 128 * 66 * 68) return;
    int b    = idx / (128 * 66 * 68);
    int rem  = idx - b * (128 * 66 * 68);
    int c2   = rem / (66 * 68);
    int rem2 = rem - c2 * (66 * 68);
    int y = rem2 / 68, x = rem2 - y * 68;
    uint16_t h0 = 0, l0 = 0, h1 = 0, l1 = 0;
    if (y >= 1 && y <= 64 && x >= 1 && x <= 64) {
        size_t base = ((size_t)(b * 256 + 2 * c2) * 64 + (y - 1)) * 64 + (x - 1);
        split_bf16(q[base], h0, l0);
        split_bf16(q[base + 4096], h1, l1);
    }
    g_i2h[idx] = (uint32_t)h0 | ((uint32_t)h1 << 16);
    g_i2l[idx] = (uint32_t)l0 | ((uint32_t)l1 << 16);
}

// offset_w (64,256,3,3) -> [tap][oc][c]
__global__ __launch_bounds__(256) void prep_w_kernel(const float* __restrict__ w) {
    int idx = blockIdx.x * 256 + threadIdx.x;
    if (idx >= 9 * 64 * 256) return;
    int tap = idx >> 14;
    int rem = idx & 16383;
    int oc = rem >> 8, c = rem & 255;
    uint16_t h, l;
    split_bf16(w[(size_t)oc * 2304 + c * 9 + tap], h, l);
    g_wch[idx] = h;
    g_wcl[idx] = l;
}

__global__ __launch_bounds__(256) void prep_pw_kernel(const float* __restrict__ w, int slot) {
    int idx = blockIdx.x * 256 + threadIdx.x;
    uint16_t h, l;
    split_bf16(w[idx], h, l);
    g_pwh[(size_t)slot * 65536 + idx] = h;
    g_pwl[(size_t)slot * 65536 + idx] = l;
}

// Transpose+split: x (B,256,Npix) fp32 -> [b][pix][c] bf16 hi/lo
__global__ __launch_bounds__(256) void tsplit_kernel(
    const float* __restrict__ x, uint16_t* __restrict__ oh,
    uint16_t* __restrict__ ol, int Npix)
{
    __shared__ float tile[32][33];
    int p0 = blockIdx.x * 32, c0 = blockIdx.y * 32, b = blockIdx.z;
    int tx = threadIdx.x & 31, ty = threadIdx.x >> 5;
    const float* src = x + ((size_t)b * 256 + c0) * Npix + p0;
#pragma unroll
    for (int lq = 0; lq < 4; lq++) {
        int cc = ty + lq * 8;
        tile[cc][tx] = src[(size_t)cc * Npix + tx];
    }
    __syncthreads();
#pragma unroll
    for (int lq = 0; lq < 4; lq++) {
        int pp = ty + lq * 8;
        uint16_t h, l;
        split_bf16(tile[tx][pp], h, l);
        size_t o = ((size_t)b * Npix + p0 + pp) * 256 + c0 + tx;
        oh[o] = h;
        ol[o] = l;
    }
}

// ---------------- PROJ / OUT split-bf16 GEMM (cp.async double-buffered) ------
enum { MODE_PROJ = 0, MODE_OUT = 1 };

// dynamic smem byte layout (u16 elements):
//   AH: [2][128*40] @0        (10240 B per buf)
//   AL: @20480
//   BH: [2][64*40]  @40960    (5120 B per buf)
//   BL: @51200     total 61440 B
#define PJ_SMEM 61440

template <int MODE>
__global__ __launch_bounds__(256) void mma_gemm(
    const uint16_t* __restrict__ Ahg, const uint16_t* __restrict__ Alg,
    const uint16_t* __restrict__ Bhg, const uint16_t* __restrict__ Blg,
    float* __restrict__ dst, int Npix, int which)
{
    extern __shared__ __align__(16) char smem[];
    const uint32_t smb = smem_u32(smem);

    const int t = threadIdx.x;
    const int lane = t & 31, wid = t >> 5;
    const int warp_m = wid & 3;
    const int warp_n = wid >> 2;
    const int bb = blockIdx.z;
    const int n0 = blockIdx.x * 64;
    const int m0 = blockIdx.y * 128;

    float c[2][4][4];
#pragma unroll
    for (int i = 0; i < 2; i++)
#pragma unroll
        for (int j = 0; j < 4; j++)
#pragma unroll
            for (int r = 0; r < 4; r++) c[i][j][r] = 0.f;

    // staging thread mapping
    const int am = t >> 1, ahalf = (t & 1) * 16;
    const int bn = t >> 2, bq = t & 3;

    auto stage = [&](int kb, int buf) {
        size_t aoff = (size_t)(m0 + am) * 256 + kb * 32 + ahalf;
        uint32_t adst = smb + buf * 10240 + (am * 40 + ahalf) * 2;
        CP16(adst, Ahg + aoff);
        CP16(adst + 16, Ahg + aoff + 8);
        CP16(adst + 20480, Alg + aoff);
        CP16(adst + 20480 + 16, Alg + aoff + 8);
        size_t boff = ((size_t)bb * Npix + n0 + bn) * 256 + kb * 32 + bq * 8;
        uint32_t bdst = smb + 40960 + buf * 5120 + (bn * 40 + bq * 8) * 2;
        CP16(bdst, Bhg + boff);
        CP16(bdst + 10240, Blg + boff);
    };

    stage(0, 0);
    CP_COMMIT();

    const int ml = warp_m * 32 + (lane >> 2);
    const int nl = warp_n * 32 + (lane >> 2);
    const int kq = lane & 3;

    for (int kb = 0; kb < 8; kb++) {
        const int buf = kb & 1;
        CP_WAIT0();
        __syncthreads();
        if (kb + 1 < 8) { stage(kb + 1, buf ^ 1); CP_COMMIT(); }

        const uint32_t* A32h = (const uint32_t*)(smem + buf * 10240);
        const uint32_t* A32l = (const uint32_t*)(smem + 20480 + buf * 10240);
        const uint32_t* B32h = (const uint32_t*)(smem + 40960 + buf * 5120);
        const uint32_t* B32l = (const uint32_t*)(smem + 51200 + buf * 5120);
#pragma unroll
        for (int ks = 0; ks < 2; ks++) {
            const int kk = ks * 8 + kq;
            uint32_t ah[2][4], al[2][4], bh4[4][2], bl4[4][2];
#pragma unroll
            for (int i = 0; i < 2; i++) {
                int base = (ml + i * 16) * 20 + kk;
                ah[i][0] = A32h[base];       ah[i][1] = A32h[base + 160];
                ah[i][2] = A32h[base + 4];   ah[i][3] = A32h[base + 164];
                al[i][0] = A32l[base];       al[i][1] = A32l[base + 160];
                al[i][2] = A32l[base + 4];   al[i][3] = A32l[base + 164];
            }
#pragma unroll
            for (int j = 0; j < 4; j++) {
                int base = (nl + j * 8) * 20 + kk;
                bh4[j][0] = B32h[base];      bh4[j][1] = B32h[base + 4];
                bl4[j][0] = B32l[base];      bl4[j][1] = B32l[base + 4];
            }
#pragma unroll
            for (int i = 0; i < 2; i++)
#pragma unroll
                for (int j = 0; j < 4; j++)
                    mma_bf16(c[i][j], ah[i], bh4[j]);
#pragma unroll
            for (int i = 0; i < 2; i++)
#pragma unroll
                for (int j = 0; j < 4; j++)
                    mma_bf16(c[i][j], ah[i], bl4[j]);
#pragma unroll
            for (int i = 0; i < 2; i++)
#pragma unroll
                for (int j = 0; j < 4; j++)
                    mma_bf16(c[i][j], al[i], bh4[j]);
        }
        __syncthreads();
    }

    // ---------------- epilogues ----------------
#pragma unroll
    for (int i = 0; i < 2; i++) {
#pragma unroll
        for (int j = 0; j < 4; j++) {
#pragma unroll
            for (int r = 0; r < 4; r++) {
                int mm = warp_m * 32 + i * 16 + (lane >> 2) + ((r & 2) ? 8 : 0);
                int nn = warp_n * 32 + j * 8 + (lane & 3) * 2 + (r & 1);
                float v = c[i][j][r];
                if (MODE == MODE_PROJ) {
                    int m = m0 + mm;
                    int n = n0 + nn;
                    int hh = m >> 5, d = m & 31;
                    float* dstp = (which == 0) ? g_q : ((which == 1) ? g_k : g_v);
                    dstp[((size_t)(bb * 8 + hh) * Npix + n) * 32 + d] = v;
                } else {
                    int m = m0 + mm;
                    int n = n0 + nn;
                    dst[((size_t)bb * 256 + m) * 4096 + n] = v;
                }
            }
        }
    }
}

// ---------------- conv kernel: window-reuse implicit GEMM --------------------
// C[oc=64][pix=128] per block. A = W [oc][c] (hi/lo, cp.async double-buffered
// per tap), B = image window [c2=16][4 rows][68] staged once per c-block and
// reused by all 9 taps.
// smem bytes: IMGH 0..17920, IMGL 17920..35840, WH [2][64][40] @35840 (10240 B),
//             WL @46080 (10240 B).  total 56320.
#define CV_SMEM 56320

__global__ __launch_bounds__(256) void conv_tc_kernel(const float* __restrict__ bias) {
    extern __shared__ __align__(16) char smem[];
    const uint32_t smb = smem_u32(smem);
    uint32_t* Ih = (uint32_t*)smem;                 // [16][280]
    uint32_t* Il = (uint32_t*)(smem + 17920);

    const int t = threadIdx.x;
    const int lane = t & 31, wid = t >> 5;
    const int warp_m = wid & 1;        // 2 x 32 oc
    const int warp_n = wid >> 1;       // 4 x 32 pix
    const int tile = blockIdx.x;       // 0..31
    const int bb = blockIdx.y;
    const int p0 = tile * 128;
    const int py0 = tile * 2;

    float c[2][4][4];
#pragma unroll
    for (int i = 0; i < 2; i++)
#pragma unroll
        for (int j = 0; j < 4; j++)
#pragma unroll
            for (int r = 0; r < 4; r++) c[i][j][r] = 0.f;

    // weight staging (cp.async): thread t covers (oc=t>>2, q=t&3), hi+lo
    auto stage_w = [&](int g, int wb) {
        int tap = g / 9, cblk = g - tap * 9;  // WRONG decomposition guard below
        // g = cblk*9 + tap  ->  cblk = g/9, tap = g%9
        cblk = g / 9; tap = g - cblk * 9;
        int oc = t >> 2, q = t & 3;
        size_t src = ((size_t)(tap * 64 + oc)) * 256 + cblk * 32 + q * 8;
        uint32_t dsth = smb + 35840 + (wb * 2560 + oc * 40 + q * 8) * 2;
        CP16(dsth, g_wch + src);
        CP16(dsth + 10240, g_wcl + src);
    };

    stage_w(0, 0);
    CP_COMMIT();

    const int ml = warp_m * 32 + (lane >> 2);
    const int kq = lane & 3;

    for (int cblk = 0; cblk < 8; cblk++) {
        __syncthreads();
        // stage image window: 16 c2 x 4 rows x 68 u32, hi+lo (coalesced uint4)
        for (int i = t; i < 1088; i += 256) {
            int rl = i / 17, xq = i - rl * 17;     // rl = c2*4 + r
            int c2 = rl >> 2, r = rl & 3;
            size_t src = (((size_t)(bb * 128 + cblk * 16 + c2)) * 66 + (py0 + r)) * 68 + xq * 4;
            int dstw = c2 * 280 + r * 68 + xq * 4;
            *(uint4*)(Ih + dstw) = *(const uint4*)(g_i2h + src);
            *(uint4*)(Il + dstw) = *(const uint4*)(g_i2l + src);
        }
        __syncthreads();

        for (int tap = 0; tap < 9; tap++) {
            const int g = cblk * 9 + tap;
            const int wb = g & 1;
            CP_WAIT0();
            __syncthreads();
            if (g + 1 < 72) { stage_w(g + 1, wb ^ 1); CP_COMMIT(); }

            const int rowoff = tap / 3;            // dy + 1
            const int xoff = tap - rowoff * 3;     // dx + 1
            const uint32_t* W32h = (const uint32_t*)(smem + 35840 + wb * 5120);
            const uint32_t* W32l = (const uint32_t*)(smem + 46080 + wb * 5120);

#pragma unroll
            for (int ks = 0; ks < 2; ks++) {
                const int kk = ks * 8 + kq;
                uint32_t ah[2][4], al[2][4], bh4[4][2], bl4[4][2];
#pragma unroll
                for (int i = 0; i < 2; i++) {
                    int base = (ml + i * 16) * 20 + kk;
                    ah[i][0] = W32h[base];       ah[i][1] = W32h[base + 160];
                    ah[i][2] = W32h[base + 4];   ah[i][3] = W32h[base + 164];
                    al[i][0] = W32l[base];       al[i][1] = W32l[base + 160];
                    al[i][2] = W32l[base + 4];   al[i][3] = W32l[base + 164];
                }
                const int c2b = ks * 8 + kq;
#pragma unroll
                for (int j = 0; j < 4; j++) {
                    int n = warp_n * 32 + j * 8 + (lane >> 2);
                    int addr = c2b * 280 + ((n >> 6) + rowoff) * 68 + (n & 63) + xoff;
                    bh4[j][0] = Ih[addr];
                    bh4[j][1] = Ih[addr + 4 * 280];
                    bl4[j][0] = Il[addr];
                    bl4[j][1] = Il[addr + 4 * 280];
                }
#pragma unroll
                for (int i = 0; i < 2; i++)
#pragma unroll
                    for (int j = 0; j < 4; j++)
                        mma_bf16(c[i][j], ah[i], bh4[j]);
#pragma unroll
                for (int i = 0; i < 2; i++)
#pragma unroll
                    for (int j = 0; j < 4; j++)
                        mma_bf16(c[i][j], ah[i], bl4[j]);
#pragma unroll
                for (int i = 0; i < 2; i++)
#pragma unroll
                    for (int j = 0; j < 4; j++)
                        mma_bf16(c[i][j], al[i], bh4[j]);
            }
        }
    }

    // ---------------- epilogue: bias + tanh + base grid -> g_grids ----------
#pragma unroll
    for (int i = 0; i < 2; i++) {
#pragma unroll
        for (int j = 0; j < 4; j++) {
#pragma unroll
            for (int r = 0; r < 4; r++) {
                int oc = warp_m * 32 + i * 16 + (lane >> 2) + ((r & 2) ? 8 : 0);
                int nn = warp_n * 32 + j * 8 + (lane & 3) * 2 + (r & 1);
                int pix = p0 + nn;
                float w = tanhf(c[i][j][r] + __ldg(&bias[oc])) * 0.25f;
                int comp = oc & 1;
                int hh = oc >> 3, p = (oc >> 1) & 3;
                int py = pix >> 6, px = pix & 63;
                float base = comp ? (py * (2.f / 63.f) - 1.f)
                                  : (px * (2.f / 63.f) - 1.f);
                g_grids[((((size_t)(bb * 8 + hh) * 4 + p) * 4096) + pix) * 2 + comp]
                    = w + base;
            }
        }
    }
}

// ----------------------------------------------------------------------------
// Fused bilinear sampling + attention; emits split-bf16 for the OUT GEMM.
// ----------------------------------------------------------------------------
__global__ __launch_bounds__(256) void attn_kernel()
{
    int gw   = blockIdx.x * 8 + (threadIdx.x >> 5);
    int lane = threadIdx.x & 31;
    int n    = gw >> 12;
    int pix  = gw & 4095;
    int b    = n >> 3;
    int hh   = n & 7;

    float qv = g_q[((size_t)n * 4096 + pix) * 32 + lane];
    const float* kb = g_k + (size_t)n * 1024 * 32;
    const float* vb = g_v + (size_t)n * 1024 * 32;
    const float2* gp = (const float2*)g_grids + (size_t)n * 4 * 4096 + pix;

    float logit[4], vs[4];
#pragma unroll
    for (int p = 0; p < 4; p++) {
        float2 g = gp[(size_t)p * 4096];
        float x = (g.x + 1.f) * 16.f - 0.5f;
        float y = (g.y + 1.f) * 16.f - 0.5f;
        float x0f = floorf(x), y0f = floorf(y);
        float wx1 = x - x0f, wy1 = y - y0f;
        int x0 = (int)x0f, y0 = (int)y0f;
        float ks = 0.f, vv = 0.f;
#pragma unroll
        for (int dy = 0; dy < 2; dy++) {
#pragma unroll
            for (int dx = 0; dx < 2; dx++) {
                int xi = x0 + dx, yi = y0 + dy;
                float w = (dx ? wx1 : 1.f - wx1) * (dy ? wy1 : 1.f - wy1);
                if ((unsigned)xi < 32u && (unsigned)yi < 32u) {
                    int off = ((yi << 5) + xi) << 5;
                    ks = fmaf(w, kb[off + lane], ks);
                    vv = fmaf(w, vb[off + lane], vv);
                }
            }
        }
        float tsum = qv * ks;
#pragma unroll
        for (int o = 16; o > 0; o >>= 1)
            tsum += __shfl_xor_sync(0xffffffffu, tsum, o);
        logit[p] = tsum * 0.17677669529663687f;
        vs[p] = vv;
    }

    float mx = fmaxf(fmaxf(logit[0], logit[1]), fmaxf(logit[2], logit[3]));
    float e0 = expf(logit[0] - mx);
    float e1 = expf(logit[1] - mx);
    float e2 = expf(logit[2] - mx);
    float e3 = expf(logit[3] - mx);
    float inv = 1.f / (e0 + e1 + e2 + e3);
    float o = (e0 * vs[0] + e1 * vs[1] + e2 * vs[2] + e3 * vs[3]) * inv;

    uint16_t h, l;
    split_bf16(o, h, l);
    size_t idx = ((size_t)b * 4096 + pix) * 256 + hh * 32 + lane;
    g_attnh[idx] = h;
    g_attnl[idx] = l;
}

// ----------------------------------------------------------------------------
extern "C" void kernel_launch(void* const* d_in, const int* in_sizes, int n_in,
                              void* d_out, int out_size)
{
    (void)in_sizes; (void)n_in; (void)out_size;
    const float* query = (const float*)d_in[0];
    const float* kv    = (const float*)d_in[1];
    const float* q_w   = (const float*)d_in[2];
    const float* k_w   = (const float*)d_in[3];
    const float* v_w   = (const float*)d_in[4];
    const float* off_w = (const float*)d_in[5];
    const float* off_b = (const float*)d_in[6];
    const float* out_w = (const float*)d_in[7];
    float* out = (float*)d_out;

    cudaFuncSetAttribute(mma_gemm<MODE_PROJ>,
                         cudaFuncAttributeMaxDynamicSharedMemorySize, PJ_SMEM);
    cudaFuncSetAttribute(mma_gemm<MODE_OUT>,
                         cudaFuncAttributeMaxDynamicSharedMemorySize, PJ_SMEM);
    cudaFuncSetAttribute(conv_tc_kernel,
                         cudaFuncAttributeMaxDynamicSharedMemorySize, CV_SMEM);

    // preps
    prep_img2_kernel<<<(8 * 128 * 66 * 68 + 255) / 256, 256>>>(query);
    prep_w_kernel<<<(9 * 64 * 256 + 255) / 256, 256>>>(off_w);
    prep_pw_kernel<<<256, 256>>>(q_w, 0);
    prep_pw_kernel<<<256, 256>>>(k_w, 1);
    prep_pw_kernel<<<256, 256>>>(v_w, 2);
    prep_pw_kernel<<<256, 256>>>(out_w, 3);

    uint16_t *xqh, *xql, *xkh, *xkl, *ath, *atl, *pwh, *pwl;
    cudaGetSymbolAddress((void**)&xqh, g_xqh);
    cudaGetSymbolAddress((void**)&xql, g_xql);
    cudaGetSymbolAddress((void**)&xkh, g_xkh);
    cudaGetSymbolAddress((void**)&xkl, g_xkl);
    cudaGetSymbolAddress((void**)&ath, g_attnh);
    cudaGetSymbolAddress((void**)&atl, g_attnl);
    cudaGetSymbolAddress((void**)&pwh, g_pwh);
    cudaGetSymbolAddress((void**)&pwl, g_pwl);

    tsplit_kernel<<<dim3(4096 / 32, 8, 8), 256>>>(query, xqh, xql, 4096);
    tsplit_kernel<<<dim3(1024 / 32, 8, 8), 256>>>(kv, xkh, xkl, 1024);

    // projections
    mma_gemm<MODE_PROJ><<<dim3(64, 2, 8), 256, PJ_SMEM>>>(
        pwh + 0 * 65536, pwl + 0 * 65536, xqh, xql, nullptr, 4096, 0);
    mma_gemm<MODE_PROJ><<<dim3(16, 2, 8), 256, PJ_SMEM>>>(
        pwh + 1 * 65536, pwl + 1 * 65536, xkh, xkl, nullptr, 1024, 1);
    mma_gemm<MODE_PROJ><<<dim3(16, 2, 8), 256, PJ_SMEM>>>(
        pwh + 2 * 65536, pwl + 2 * 65536, xkh, xkl, nullptr, 1024, 2);

    // offset conv -> grids
    conv_tc_kernel<<<dim3(32, 8), 256, CV_SMEM>>>(off_b);

    // fused bilinear sample + attention -> split attn
    attn_kernel<<<(64 * 4096) / 8, 256>>>();

    // output projection -> d_out
    mma_gemm<MODE_OUT><<<dim3(64, 2, 8), 256, PJ_SMEM>>>(
        pwh + 3 * 65536, pwl + 3 * 65536, ath, atl, out, 4096, 0);
}

// round 6
// speedup vs baseline: 2.3682x; 1.0448x over previous
#include <cuda_runtime.h>
#include <cuda_bf16.h>
#include <math.h>
#include <stdint.h>

// ----------------------------------------------------------------------------
// DeformableCrossAttention2D, split-bf16 mma.sync + ldmatrix (sm_100-safe).
//   query_map: (8, 256, 64, 64)   kv_map: (8, 256, 32, 32)
//   q_w/k_w/v_w/out_w: (256,256)  offset_w: (64,256,3,3)  offset_b: (64)
//   heads H=8, points P=4, D=32;  output: (8, 256, 64, 64) float32
// ----------------------------------------------------------------------------

// ---------------- scratch (device globals; allocation-free rule) -------------
__device__ float g_q[64 * 4096 * 32];        // (n=b*H, pix, d)
__device__ float g_k[64 * 1024 * 32];
__device__ float g_v[64 * 1024 * 32];
__device__ float g_grids[64 * 4 * 4096 * 2]; // (n, p, pix, {x,y})

// c-pair-interleaved padded image planes: [b][c2=128][y=66][x=68] u32
__device__ __align__(16) uint32_t g_i2h[8 * 128 * 66 * 68];
__device__ __align__(16) uint32_t g_i2l[8 * 128 * 66 * 68];
__device__ __align__(16) uint16_t g_wch[9 * 64 * 256];   // conv W [tap][oc][c] hi
__device__ __align__(16) uint16_t g_wcl[9 * 64 * 256];
__device__ __align__(16) uint16_t g_pwh[4 * 256 * 256];  // proj/out W [slot][m][k]
__device__ __align__(16) uint16_t g_pwl[4 * 256 * 256];
__device__ __align__(16) uint16_t g_xqh[8 * 4096 * 256]; // query^T [b][pix][c]
__device__ __align__(16) uint16_t g_xql[8 * 4096 * 256];
__device__ __align__(16) uint16_t g_xkh[8 * 1024 * 256]; // kv^T
__device__ __align__(16) uint16_t g_xkl[8 * 1024 * 256];
__device__ __align__(16) uint16_t g_attnh[8 * 4096 * 256];
__device__ __align__(16) uint16_t g_attnl[8 * 4096 * 256];

// ---------------- helpers ----------------------------------------------------
__device__ __forceinline__ void split_bf16(float v, uint16_t& h, uint16_t& l) {
    __nv_bfloat16 hb = __float2bfloat16(v);
    float r = v - __bfloat162float(hb);
    h = __bfloat16_as_ushort(hb);
    l = __bfloat16_as_ushort(__float2bfloat16(r));
}

__device__ __forceinline__ void mma_bf16(float* c, const uint32_t* a, const uint32_t* b) {
    asm volatile(
        "mma.sync.aligned.m16n8k16.row.col.f32.bf16.bf16.f32 "
        "{%0,%1,%2,%3}, {%4,%5,%6,%7}, {%8,%9}, {%0,%1,%2,%3};"
        : "+f"(c[0]), "+f"(c[1]), "+f"(c[2]), "+f"(c[3])
        : "r"(a[0]), "r"(a[1]), "r"(a[2]), "r"(a[3]), "r"(b[0]), "r"(b[1]));
}

__device__ __forceinline__ void ldm_x4(uint32_t* r, uint32_t addr) {
    asm volatile("ldmatrix.sync.aligned.m8n8.x4.shared.b16 {%0,%1,%2,%3}, [%4];"
                 : "=r"(r[0]), "=r"(r[1]), "=r"(r[2]), "=r"(r[3]) : "r"(addr));
}

__device__ __forceinline__ uint32_t smem_u32(const void* p) {
    uint32_t a;
    asm("{ .reg .u64 t; cvta.to.shared.u64 t, %1; cvt.u32.u64 %0, t; }" : "=r"(a) : "l"(p));
    return a;
}
#define CP16(dst, src) \
    asm volatile("cp.async.cg.shared.global [%0], [%1], 16;" :: "r"(dst), "l"(src) : "memory")
#define CP_COMMIT() asm volatile("cp.async.commit_group;" ::: "memory")
#define CP_WAIT0()  asm volatile("cp.async.wait_group 0;" ::: "memory")

// ---------------- prep kernels -----------------------------------------------
__global__ __launch_bounds__(256) void prep_img2_kernel(const float* __restrict__ q) {
    int idx = blockIdx.x * 256 + threadIdx.x;
    if (idx >= 8 * 128 * 66 * 68) return;
    int b    = idx / (128 * 66 * 68);
    int rem  = idx - b * (128 * 66 * 68);
    int c2   = rem / (66 * 68);
    int rem2 = rem - c2 * (66 * 68);
    int y = rem2 / 68, x = rem2 - y * 68;
    uint16_t h0 = 0, l0 = 0, h1 = 0, l1 = 0;
    if (y >= 1 && y <= 64 && x >= 1 && x <= 64) {
        size_t base = ((size_t)(b * 256 + 2 * c2) * 64 + (y - 1)) * 64 + (x - 1);
        split_bf16(q[base], h0, l0);
        split_bf16(q[base + 4096], h1, l1);
    }
    g_i2h[idx] = (uint32_t)h0 | ((uint32_t)h1 << 16);
    g_i2l[idx] = (uint32_t)l0 | ((uint32_t)l1 << 16);
}

__global__ __launch_bounds__(256) void prep_w_kernel(const float* __restrict__ w) {
    int idx = blockIdx.x * 256 + threadIdx.x;
    if (idx >= 9 * 64 * 256) return;
    int tap = idx >> 14;
    int rem = idx & 16383;
    int oc = rem >> 8, c = rem & 255;
    uint16_t h, l;
    split_bf16(w[(size_t)oc * 2304 + c * 9 + tap], h, l);
    g_wch[idx] = h;
    g_wcl[idx] = l;
}

// All four 256x256 projection weights in one launch (blockIdx.y = slot)
__global__ __launch_bounds__(256) void prep_pw_kernel(
    const float* __restrict__ w0, const float* __restrict__ w1,
    const float* __restrict__ w2, const float* __restrict__ w3)
{
    int slot = blockIdx.y;
    const float* w = (slot == 0) ? w0 : (slot == 1) ? w1 : (slot == 2) ? w2 : w3;
    int idx = blockIdx.x * 256 + threadIdx.x;
    uint16_t h, l;
    split_bf16(w[idx], h, l);
    g_pwh[(size_t)slot * 65536 + idx] = h;
    g_pwl[(size_t)slot * 65536 + idx] = l;
}

__global__ __launch_bounds__(256) void tsplit_kernel(
    const float* __restrict__ x, uint16_t* __restrict__ oh,
    uint16_t* __restrict__ ol, int Npix)
{
    __shared__ float tile[32][33];
    int p0 = blockIdx.x * 32, c0 = blockIdx.y * 32, b = blockIdx.z;
    int tx = threadIdx.x & 31, ty = threadIdx.x >> 5;
    const float* src = x + ((size_t)b * 256 + c0) * Npix + p0;
#pragma unroll
    for (int lq = 0; lq < 4; lq++) {
        int cc = ty + lq * 8;
        tile[cc][tx] = src[(size_t)cc * Npix + tx];
    }
    __syncthreads();
#pragma unroll
    for (int lq = 0; lq < 4; lq++) {
        int pp = ty + lq * 8;
        uint16_t h, l;
        split_bf16(tile[tx][pp], h, l);
        size_t o = ((size_t)b * Npix + p0 + pp) * 256 + c0 + tx;
        oh[o] = h;
        ol[o] = l;
    }
}

// ---------------- PROJ / OUT split-bf16 GEMM (cp.async + ldmatrix) -----------
enum { MODE_PROJ = 0, MODE_OUT = 1 };

// dynamic smem byte layout (u16, rows padded to 40):
//   AH: [2][128*40] @0        AL: @20480
//   BH: [2][64*40]  @40960    BL: @51200   total 61440 B
#define PJ_SMEM 61440

template <int MODE>
__global__ __launch_bounds__(256) void mma_gemm(
    const uint16_t* __restrict__ Ahg, const uint16_t* __restrict__ Alg,
    const uint16_t* __restrict__ Bhg, const uint16_t* __restrict__ Blg,
    float* __restrict__ dst, int Npix, int which)
{
    extern __shared__ __align__(16) char smem[];
    const uint32_t smb = smem_u32(smem);

    const int t = threadIdx.x;
    const int lane = t & 31, wid = t >> 5;
    const int warp_m = wid & 3;
    const int warp_n = wid >> 2;
    const int bb = blockIdx.z;
    const int n0 = blockIdx.x * 64;
    const int m0 = blockIdx.y * 128;

    float c[2][4][4];
#pragma unroll
    for (int i = 0; i < 2; i++)
#pragma unroll
        for (int j = 0; j < 4; j++)
#pragma unroll
            for (int r = 0; r < 4; r++) c[i][j][r] = 0.f;

    const int am = t >> 1, ahalf = (t & 1) * 16;
    const int bn = t >> 2, bq = t & 3;

    auto stage = [&](int kb, int buf) {
        size_t aoff = (size_t)(m0 + am) * 256 + kb * 32 + ahalf;
        uint32_t adst = smb + buf * 10240 + (am * 40 + ahalf) * 2;
        CP16(adst, Ahg + aoff);
        CP16(adst + 16, Ahg + aoff + 8);
        CP16(adst + 20480, Alg + aoff);
        CP16(adst + 20480 + 16, Alg + aoff + 8);
        size_t boff = ((size_t)bb * Npix + n0 + bn) * 256 + kb * 32 + bq * 8;
        uint32_t bdst = smb + 40960 + buf * 5120 + (bn * 40 + bq * 8) * 2;
        CP16(bdst, Bhg + boff);
        CP16(bdst + 10240, Blg + boff);
    };

    stage(0, 0);
    CP_COMMIT();

    // ldmatrix lane addressing (bytes, relative to operand base)
    // A: lanes 0-7 rows+0..7 @k0 | 8-15 rows+8..15 @k0 | 16-23 rows @k8 | 24-31 rows+8 @k8
    const uint32_t aAddr = ((warp_m * 32 + (lane & 15)) * 40 + ((lane >> 4) * 8)) * 2;
    // B: lanes 0-7 n+0..7 @k0 | 8-15 n+0..7 @k8 | 16-23 n+8..15 @k0 | 24-31 n+8..15 @k8
    const uint32_t bAddr = ((warp_n * 32 + (lane & 7) + ((lane >> 4) << 3)) * 40
                            + (((lane >> 3) & 1) * 8)) * 2;

    for (int kb = 0; kb < 8; kb++) {
        const int buf = kb & 1;
        CP_WAIT0();
        __syncthreads();
        if (kb + 1 < 8) { stage(kb + 1, buf ^ 1); CP_COMMIT(); }

        const uint32_t baseAh = smb + buf * 10240 + aAddr;
        const uint32_t baseAl = smb + 20480 + buf * 10240 + aAddr;
        const uint32_t baseBh = smb + 40960 + buf * 5120 + bAddr;
        const uint32_t baseBl = smb + 51200 + buf * 5120 + bAddr;
#pragma unroll
        for (int ks = 0; ks < 2; ks++) {
            uint32_t ah[2][4], al[2][4], bh4[4][4], bl4[4][4];
            ldm_x4(ah[0], baseAh + ks * 32);
            ldm_x4(ah[1], baseAh + ks * 32 + 1280);
            ldm_x4(al[0], baseAl + ks * 32);
            ldm_x4(al[1], baseAl + ks * 32 + 1280);
            ldm_x4(bh4[0], baseBh + ks * 32);          // j tiles 0,1
            ldm_x4(bh4[2], baseBh + ks * 32 + 1280);   // j tiles 2,3
            ldm_x4(bl4[0], baseBl + ks * 32);
            ldm_x4(bl4[2], baseBl + ks * 32 + 1280);
            // b fragment for tile j: {reg[2*(j&1)], reg[2*(j&1)+1]} of pair (j>>1)
            uint32_t bfh[4][2], bfl[4][2];
#pragma unroll
            for (int j = 0; j < 4; j++) {
                bfh[j][0] = bh4[(j >> 1) * 2][(j & 1) * 2 + 0];
                bfh[j][1] = bh4[(j >> 1) * 2][(j & 1) * 2 + 1];
                bfl[j][0] = bl4[(j >> 1) * 2][(j & 1) * 2 + 0];
                bfl[j][1] = bl4[(j >> 1) * 2][(j & 1) * 2 + 1];
            }
#pragma unroll
            for (int i = 0; i < 2; i++)
#pragma unroll
                for (int j = 0; j < 4; j++)
                    mma_bf16(c[i][j], ah[i], bfh[j]);
#pragma unroll
            for (int i = 0; i < 2; i++)
#pragma unroll
                for (int j = 0; j < 4; j++)
                    mma_bf16(c[i][j], ah[i], bfl[j]);
#pragma unroll
            for (int i = 0; i < 2; i++)
#pragma unroll
                for (int j = 0; j < 4; j++)
                    mma_bf16(c[i][j], al[i], bfh[j]);
        }
        __syncthreads();
    }

    // ---------------- epilogues ----------------
#pragma unroll
    for (int i = 0; i < 2; i++) {
#pragma unroll
        for (int j = 0; j < 4; j++) {
#pragma unroll
            for (int r = 0; r < 4; r++) {
                int mm = warp_m * 32 + i * 16 + (lane >> 2) + ((r & 2) ? 8 : 0);
                int nn = warp_n * 32 + j * 8 + (lane & 3) * 2 + (r & 1);
                float v = c[i][j][r];
                if (MODE == MODE_PROJ) {
                    int m = m0 + mm;
                    int n = n0 + nn;
                    int hh = m >> 5, d = m & 31;
                    float* dstp = (which == 0) ? g_q : ((which == 1) ? g_k : g_v);
                    dstp[((size_t)(bb * 8 + hh) * Npix + n) * 32 + d] = v;
                } else {
                    int m = m0 + mm;
                    int n = n0 + nn;
                    dst[((size_t)bb * 256 + m) * 4096 + n] = v;
                }
            }
        }
    }
}

// ---------------- conv kernel: window-reuse implicit GEMM --------------------
// C[oc=64][pix=128] per block. A = W [oc][c] (ldmatrix, cp.async dbl-buffered),
// B = image window [c2=16][4 rows][68] staged once per c-block, 9 taps reuse.
// smem: IMGH 0..17920, IMGL 17920..35840, WH [2][64][40] @35840, WL @46080.
#define CV_SMEM 56320

__global__ __launch_bounds__(256) void conv_tc_kernel(const float* __restrict__ bias) {
    extern __shared__ __align__(16) char smem[];
    const uint32_t smb = smem_u32(smem);
    uint32_t* Ih = (uint32_t*)smem;                 // [16][280]
    uint32_t* Il = (uint32_t*)(smem + 17920);

    const int t = threadIdx.x;
    const int lane = t & 31, wid = t >> 5;
    const int warp_m = wid & 1;        // 2 x 32 oc
    const int warp_n = wid >> 1;       // 4 x 32 pix
    const int tile = blockIdx.x;
    const int bb = blockIdx.y;
    const int p0 = tile * 128;
    const int py0 = tile * 2;

    float c[2][4][4];
#pragma unroll
    for (int i = 0; i < 2; i++)
#pragma unroll
        for (int j = 0; j < 4; j++)
#pragma unroll
            for (int r = 0; r < 4; r++) c[i][j][r] = 0.f;

    auto stage_w = [&](int g, int wb) {
        int cblk = g / 9, tap = g - cblk * 9;
        int oc = t >> 2, q = t & 3;
        size_t src = ((size_t)(tap * 64 + oc)) * 256 + cblk * 32 + q * 8;
        uint32_t dsth = smb + 35840 + (wb * 2560 + oc * 40 + q * 8) * 2;
        CP16(dsth, g_wch + src);
        CP16(dsth + 10240, g_wcl + src);
    };

    stage_w(0, 0);
    CP_COMMIT();

    const uint32_t aAddr = ((warp_m * 32 + (lane & 15)) * 40 + ((lane >> 4) * 8)) * 2;
    const int kq = lane & 3;

    for (int cblk = 0; cblk < 8; cblk++) {
        __syncthreads();
        for (int i = t; i < 1088; i += 256) {
            int rl = i / 17, xq = i - rl * 17;
            int c2 = rl >> 2, r = rl & 3;
            size_t src = (((size_t)(bb * 128 + cblk * 16 + c2)) * 66 + (py0 + r)) * 68 + xq * 4;
            int dstw = c2 * 280 + r * 68 + xq * 4;
            *(uint4*)(Ih + dstw) = *(const uint4*)(g_i2h + src);
            *(uint4*)(Il + dstw) = *(const uint4*)(g_i2l + src);
        }
        __syncthreads();

        for (int tap = 0; tap < 9; tap++) {
            const int g = cblk * 9 + tap;
            const int wb = g & 1;
            CP_WAIT0();
            __syncthreads();
            if (g + 1 < 72) { stage_w(g + 1, wb ^ 1); CP_COMMIT(); }

            const int rowoff = tap / 3;
            const int xoff = tap - rowoff * 3;
            const uint32_t baseWh = smb + 35840 + wb * 5120 + aAddr;
            const uint32_t baseWl = smb + 46080 + wb * 5120 + aAddr;

#pragma unroll
            for (int ks = 0; ks < 2; ks++) {
                uint32_t ah[2][4], al[2][4], bh4[4][2], bl4[4][2];
                ldm_x4(ah[0], baseWh + ks * 32);
                ldm_x4(ah[1], baseWh + ks * 32 + 1280);
                ldm_x4(al[0], baseWl + ks * 32);
                ldm_x4(al[1], baseWl + ks * 32 + 1280);
                const int c2b = ks * 8 + kq;
#pragma unroll
                for (int j = 0; j < 4; j++) {
                    int n = warp_n * 32 + j * 8 + (lane >> 2);
                    int addr = c2b * 280 + ((n >> 6) + rowoff) * 68 + (n & 63) + xoff;
                    bh4[j][0] = Ih[addr];
                    bh4[j][1] = Ih[addr + 4 * 280];
                    bl4[j][0] = Il[addr];
                    bl4[j][1] = Il[addr + 4 * 280];
                }
#pragma unroll
                for (int i = 0; i < 2; i++)
#pragma unroll
                    for (int j = 0; j < 4; j++)
                        mma_bf16(c[i][j], ah[i], bh4[j]);
#pragma unroll
                for (int i = 0; i < 2; i++)
#pragma unroll
                    for (int j = 0; j < 4; j++)
                        mma_bf16(c[i][j], ah[i], bl4[j]);
#pragma unroll
                for (int i = 0; i < 2; i++)
#pragma unroll
                    for (int j = 0; j < 4; j++)
                        mma_bf16(c[i][j], al[i], bh4[j]);
            }
        }
    }

    // ---------------- epilogue: bias + tanh + base grid -> g_grids ----------
#pragma unroll
    for (int i = 0; i < 2; i++) {
#pragma unroll
        for (int j = 0; j < 4; j++) {
#pragma unroll
            for (int r = 0; r < 4; r++) {
                int oc = warp_m * 32 + i * 16 + (lane >> 2) + ((r & 2) ? 8 : 0);
                int nn = warp_n * 32 + j * 8 + (lane & 3) * 2 + (r & 1);
                int pix = p0 + nn;
                float w = tanhf(c[i][j][r] + __ldg(&bias[oc])) * 0.25f;
                int comp = oc & 1;
                int hh = oc >> 3, p = (oc >> 1) & 3;
                int py = pix >> 6, px = pix & 63;
                float base = comp ? (py * (2.f / 63.f) - 1.f)
                                  : (px * (2.f / 63.f) - 1.f);
                g_grids[((((size_t)(bb * 8 + hh) * 4 + p) * 4096) + pix) * 2 + comp]
                    = w + base;
            }
        }
    }
}

// ----------------------------------------------------------------------------
// Fused bilinear sampling + attention; emits split-bf16 for the OUT GEMM.
// ----------------------------------------------------------------------------
__global__ __launch_bounds__(256) void attn_kernel()
{
    int gw   = blockIdx.x * 8 + (threadIdx.x >> 5);
    int lane = threadIdx.x & 31;
    int n    = gw >> 12;
    int pix  = gw & 4095;
    int b    = n >> 3;
    int hh   = n & 7;

    float qv = g_q[((size_t)n * 4096 + pix) * 32 + lane];
    const float* kb = g_k + (size_t)n * 1024 * 32;
    const float* vb = g_v + (size_t)n * 1024 * 32;
    const float2* gp = (const float2*)g_grids + (size_t)n * 4 * 4096 + pix;

    float logit[4], vs[4];
#pragma unroll
    for (int p = 0; p < 4; p++) {
        float2 g = gp[(size_t)p * 4096];
        float x = (g.x + 1.f) * 16.f - 0.5f;
        float y = (g.y + 1.f) * 16.f - 0.5f;
        float x0f = floorf(x), y0f = floorf(y);
        float wx1 = x - x0f, wy1 = y - y0f;
        int x0 = (int)x0f, y0 = (int)y0f;
        float ks = 0.f, vv = 0.f;
#pragma unroll
        for (int dy = 0; dy < 2; dy++) {
#pragma unroll
            for (int dx = 0; dx < 2; dx++) {
                int xi = x0 + dx, yi = y0 + dy;
                float w = (dx ? wx1 : 1.f - wx1) * (dy ? wy1 : 1.f - wy1);
                if ((unsigned)xi < 32u && (unsigned)yi < 32u) {
                    int off = ((yi << 5) + xi) << 5;
                    ks = fmaf(w, kb[off + lane], ks);
                    vv = fmaf(w, vb[off + lane], vv);
                }
            }
        }
        float tsum = qv * ks;
#pragma unroll
        for (int o = 16; o > 0; o >>= 1)
            tsum += __shfl_xor_sync(0xffffffffu, tsum, o);
        logit[p] = tsum * 0.17677669529663687f;
        vs[p] = vv;
    }

    float mx = fmaxf(fmaxf(logit[0], logit[1]), fmaxf(logit[2], logit[3]));
    float e0 = expf(logit[0] - mx);
    float e1 = expf(logit[1] - mx);
    float e2 = expf(logit[2] - mx);
    float e3 = expf(logit[3] - mx);
    float inv = 1.f / (e0 + e1 + e2 + e3);
    float o = (e0 * vs[0] + e1 * vs[1] + e2 * vs[2] + e3 * vs[3]) * inv;

    uint16_t h, l;
    split_bf16(o, h, l);
    size_t idx = ((size_t)b * 4096 + pix) * 256 + hh * 32 + lane;
    g_attnh[idx] = h;
    g_attnl[idx] = l;
}

// ----------------------------------------------------------------------------
extern "C" void kernel_launch(void* const* d_in, const int* in_sizes, int n_in,
                              void* d_out, int out_size)
{
    (void)in_sizes; (void)n_in; (void)out_size;
    const float* query = (const float*)d_in[0];
    const float* kv    = (const float*)d_in[1];
    const float* q_w   = (const float*)d_in[2];
    const float* k_w   = (const float*)d_in[3];
    const float* v_w   = (const float*)d_in[4];
    const float* off_w = (const float*)d_in[5];
    const float* off_b = (const float*)d_in[6];
    const float* out_w = (const float*)d_in[7];
    float* out = (float*)d_out;

    cudaFuncSetAttribute(mma_gemm<MODE_PROJ>,
                         cudaFuncAttributeMaxDynamicSharedMemorySize, PJ_SMEM);
    cudaFuncSetAttribute(mma_gemm<MODE_OUT>,
                         cudaFuncAttributeMaxDynamicSharedMemorySize, PJ_SMEM);
    cudaFuncSetAttribute(conv_tc_kernel,
                         cudaFuncAttributeMaxDynamicSharedMemorySize, CV_SMEM);

    // preps
    prep_img2_kernel<<<(8 * 128 * 66 * 68 + 255) / 256, 256>>>(query);
    prep_w_kernel<<<(9 * 64 * 256 + 255) / 256, 256>>>(off_w);
    prep_pw_kernel<<<dim3(256, 4), 256>>>(q_w, k_w, v_w, out_w);

    uint16_t *xqh, *xql, *xkh, *xkl, *ath, *atl, *pwh, *pwl;
    cudaGetSymbolAddress((void**)&xqh, g_xqh);
    cudaGetSymbolAddress((void**)&xql, g_xql);
    cudaGetSymbolAddress((void**)&xkh, g_xkh);
    cudaGetSymbolAddress((void**)&xkl, g_xkl);
    cudaGetSymbolAddress((void**)&ath, g_attnh);
    cudaGetSymbolAddress((void**)&atl, g_attnl);
    cudaGetSymbolAddress((void**)&pwh, g_pwh);
    cudaGetSymbolAddress((void**)&pwl, g_pwl);

    tsplit_kernel<<<dim3(4096 / 32, 8, 8), 256>>>(query, xqh, xql, 4096);
    tsplit_kernel<<<dim3(1024 / 32, 8, 8), 256>>>(kv, xkh, xkl, 1024);

    // projections
    mma_gemm<MODE_PROJ><<<dim3(64, 2, 8), 256, PJ_SMEM>>>(
        pwh + 0 * 65536, pwl + 0 * 65536, xqh, xql, nullptr, 4096, 0);
    mma_gemm<MODE_PROJ><<<dim3(16, 2, 8), 256, PJ_SMEM>>>(
        pwh + 1 * 65536, pwl + 1 * 65536, xkh, xkl, nullptr, 1024, 1);
    mma_gemm<MODE_PROJ><<<dim3(16, 2, 8), 256, PJ_SMEM>>>(
        pwh + 2 * 65536, pwl + 2 * 65536, xkh, xkl, nullptr, 1024, 2);

    // offset conv -> grids
    conv_tc_kernel<<<dim3(32, 8), 256, CV_SMEM>>>(off_b);

    // fused bilinear sample + attention -> split attn
    attn_kernel<<<(64 * 4096) / 8, 256>>>();

    // output projection -> d_out
    mma_gemm<MODE_OUT><<<dim3(64, 2, 8), 256, PJ_SMEM>>>(
        pwh + 3 * 65536, pwl + 3 * 65536, ath, atl, out, 4096, 0);
}

// round 7
// speedup vs baseline: 2.6590x; 1.1228x over previous
#include <cuda_runtime.h>
#include <cuda_fp16.h>
#include <math.h>
#include <stdint.h>

// ----------------------------------------------------------------------------
// DeformableCrossAttention2D, split-fp16 mma.sync + ldmatrix (sm_100-safe).
//   query_map: (8, 256, 64, 64)   kv_map: (8, 256, 32, 32)
//   q_w/k_w/v_w/out_w: (256,256)  offset_w: (64,256,3,3)  offset_b: (64)
//   heads H=8, points P=4, D=32;  output: (8, 256, 64, 64) float32
// Value-path GEMMs (q/k/v/out): 2-product split fp16  (D = Ah*Bh + Ah*Bl)
// Offset conv: 3-product split fp16 (position errors amplify ~6x via sampling)
// ----------------------------------------------------------------------------

// ---------------- scratch (device globals; allocation-free rule) -------------
__device__ float g_q[64 * 4096 * 32];        // (n=b*H, pix, d)
__device__ float g_k[64 * 1024 * 32];
__device__ float g_v[64 * 1024 * 32];
__device__ float g_grids[64 * 4 * 4096 * 2]; // (n, p, pix, {x,y})

// c-pair-interleaved padded image planes: [b][c2=128][y=66][x=68] u32 (fp16 pair)
__device__ __align__(16) uint32_t g_i2h[8 * 128 * 66 * 68];
__device__ __align__(16) uint32_t g_i2l[8 * 128 * 66 * 68];
__device__ __align__(16) uint16_t g_wch[9 * 64 * 256];   // conv W [tap][oc][c] hi
__device__ __align__(16) uint16_t g_wcl[9 * 64 * 256];   // conv W lo (3-product)
__device__ __align__(16) uint16_t g_pwh[4 * 256 * 256];  // proj/out W hi only
__device__ __align__(16) uint16_t g_xqh[8 * 4096 * 256]; // query^T [b][pix][c]
__device__ __align__(16) uint16_t g_xql[8 * 4096 * 256];
__device__ __align__(16) uint16_t g_xkh[8 * 1024 * 256]; // kv^T
__device__ __align__(16) uint16_t g_xkl[8 * 1024 * 256];
__device__ __align__(16) uint16_t g_attnh[8 * 4096 * 256];
__device__ __align__(16) uint16_t g_attnl[8 * 4096 * 256];

// ---------------- helpers ----------------------------------------------------
__device__ __forceinline__ void split_f16(float v, uint16_t& h, uint16_t& l) {
    __half hb = __float2half_rn(v);
    float r = v - __half2float(hb);
    h = __half_as_ushort(hb);
    l = __half_as_ushort(__float2half_rn(r));
}

__device__ __forceinline__ void mma_f16(float* c, const uint32_t* a, const uint32_t* b) {
    asm volatile(
        "mma.sync.aligned.m16n8k16.row.col.f32.f16.f16.f32 "
        "{%0,%1,%2,%3}, {%4,%5,%6,%7}, {%8,%9}, {%0,%1,%2,%3};"
        : "+f"(c[0]), "+f"(c[1]), "+f"(c[2]), "+f"(c[3])
        : "r"(a[0]), "r"(a[1]), "r"(a[2]), "r"(a[3]), "r"(b[0]), "r"(b[1]));
}

__device__ __forceinline__ void ldm_x4(uint32_t* r, uint32_t addr) {
    asm volatile("ldmatrix.sync.aligned.m8n8.x4.shared.b16 {%0,%1,%2,%3}, [%4];"
                 : "=r"(r[0]), "=r"(r[1]), "=r"(r[2]), "=r"(r[3]) : "r"(addr));
}

__device__ __forceinline__ uint32_t smem_u32(const void* p) {
    uint32_t a;
    asm("{ .reg .u64 t; cvta.to.shared.u64 t, %1; cvt.u32.u64 %0, t; }" : "=r"(a) : "l"(p));
    return a;
}
#define CP16(dst, src) \
    asm volatile("cp.async.cg.shared.global [%0], [%1], 16;" :: "r"(dst), "l"(src) : "memory")
#define CP_COMMIT() asm volatile("cp.async.commit_group;" ::: "memory")
#define CP_WAIT0()  asm volatile("cp.async.wait_group 0;" ::: "memory")

// ---------------- prep kernels -----------------------------------------------
__global__ __launch_bounds__(256) void prep_img2_kernel(const float* __restrict__ q) {
    int idx = blockIdx.x * 256 + threadIdx.x;
    if (idx >= 8 * 128 * 66 * 68) return;
    int b    = idx / (128 * 66 * 68);
    int rem  = idx - b * (128 * 66 * 68);
    int c2   = rem / (66 * 68);
    int rem2 = rem - c2 * (66 * 68);
    int y = rem2 / 68, x = rem2 - y * 68;
    uint16_t h0 = 0, l0 = 0, h1 = 0, l1 = 0;
    if (y >= 1 && y <= 64 && x >= 1 && x <= 64) {
        size_t base = ((size_t)(b * 256 + 2 * c2) * 64 + (y - 1)) * 64 + (x - 1);
        split_f16(q[base], h0, l0);
        split_f16(q[base + 4096], h1, l1);
    }
    g_i2h[idx] = (uint32_t)h0 | ((uint32_t)h1 << 16);
    g_i2l[idx] = (uint32_t)l0 | ((uint32_t)l1 << 16);
}

__global__ __launch_bounds__(256) void prep_w_kernel(const float* __restrict__ w) {
    int idx = blockIdx.x * 256 + threadIdx.x;
    if (idx >= 9 * 64 * 256) return;
    int tap = idx >> 14;
    int rem = idx & 16383;
    int oc = rem >> 8, c = rem & 255;
    uint16_t h, l;
    split_f16(w[(size_t)oc * 2304 + c * 9 + tap], h, l);
    g_wch[idx] = h;
    g_wcl[idx] = l;
}

// All four 256x256 projection weights (hi only) in one launch
__global__ __launch_bounds__(256) void prep_pw_kernel(
    const float* __restrict__ w0, const float* __restrict__ w1,
    const float* __restrict__ w2, const float* __restrict__ w3)
{
    int slot = blockIdx.y;
    const float* w = (slot == 0) ? w0 : (slot == 1) ? w1 : (slot == 2) ? w2 : w3;
    int idx = blockIdx.x * 256 + threadIdx.x;
    g_pwh[(size_t)slot * 65536 + idx] = __half_as_ushort(__float2half_rn(w[idx]));
}

__global__ __launch_bounds__(256) void tsplit_kernel(
    const float* __restrict__ x, uint16_t* __restrict__ oh,
    uint16_t* __restrict__ ol, int Npix)
{
    __shared__ float tile[32][33];
    int p0 = blockIdx.x * 32, c0 = blockIdx.y * 32, b = blockIdx.z;
    int tx = threadIdx.x & 31, ty = threadIdx.x >> 5;
    const float* src = x + ((size_t)b * 256 + c0) * Npix + p0;
#pragma unroll
    for (int lq = 0; lq < 4; lq++) {
        int cc = ty + lq * 8;
        tile[cc][tx] = src[(size_t)cc * Npix + tx];
    }
    __syncthreads();
#pragma unroll
    for (int lq = 0; lq < 4; lq++) {
        int pp = ty + lq * 8;
        uint16_t h, l;
        split_f16(tile[tx][pp], h, l);
        size_t o = ((size_t)b * Npix + p0 + pp) * 256 + c0 + tx;
        oh[o] = h;
        ol[o] = l;
    }
}

// ---------------- PROJ / OUT 2-product fp16 GEMM (cp.async + ldmatrix) -------
enum { MODE_PROJ = 0, MODE_OUT = 1 };

// smem (u16, rows padded to 40):
//   AH: [2][128*40] @0 (10240 B/buf)   BH: [2][64*40] @20480 (5120 B/buf)
//   BL: [2][64*40] @30720              total 40960 B
#define PJ_SMEM 40960

template <int MODE>
__global__ __launch_bounds__(256) void mma_gemm(
    const uint16_t* __restrict__ Ahg,
    const uint16_t* __restrict__ Bhg, const uint16_t* __restrict__ Blg,
    float* __restrict__ dst, int Npix, int which)
{
    extern __shared__ __align__(16) char smem[];
    const uint32_t smb = smem_u32(smem);

    const int t = threadIdx.x;
    const int lane = t & 31, wid = t >> 5;
    const int warp_m = wid & 3;
    const int warp_n = wid >> 2;
    const int bb = blockIdx.z;
    const int n0 = blockIdx.x * 64;
    const int m0 = blockIdx.y * 128;

    float c[2][4][4];
#pragma unroll
    for (int i = 0; i < 2; i++)
#pragma unroll
        for (int j = 0; j < 4; j++)
#pragma unroll
            for (int r = 0; r < 4; r++) c[i][j][r] = 0.f;

    const int am = t >> 1, ahalf = (t & 1) * 16;
    const int bn = t >> 2, bq = t & 3;

    auto stage = [&](int kb, int buf) {
        size_t aoff = (size_t)(m0 + am) * 256 + kb * 32 + ahalf;
        uint32_t adst = smb + buf * 10240 + (am * 40 + ahalf) * 2;
        CP16(adst, Ahg + aoff);
        CP16(adst + 16, Ahg + aoff + 8);
        size_t boff = ((size_t)bb * Npix + n0 + bn) * 256 + kb * 32 + bq * 8;
        uint32_t bdst = smb + 20480 + buf * 5120 + (bn * 40 + bq * 8) * 2;
        CP16(bdst, Bhg + boff);
        CP16(bdst + 10240, Blg + boff);
    };

    stage(0, 0);
    CP_COMMIT();

    const uint32_t aAddr = ((warp_m * 32 + (lane & 15)) * 40 + ((lane >> 4) * 8)) * 2;
    const uint32_t bAddr = ((warp_n * 32 + (lane & 7) + ((lane >> 4) << 3)) * 40
                            + (((lane >> 3) & 1) * 8)) * 2;

    for (int kb = 0; kb < 8; kb++) {
        const int buf = kb & 1;
        CP_WAIT0();
        __syncthreads();
        if (kb + 1 < 8) { stage(kb + 1, buf ^ 1); CP_COMMIT(); }

        const uint32_t baseAh = smb + buf * 10240 + aAddr;
        const uint32_t baseBh = smb + 20480 + buf * 5120 + bAddr;
        const uint32_t baseBl = smb + 30720 + buf * 5120 + bAddr;
#pragma unroll
        for (int ks = 0; ks < 2; ks++) {
            uint32_t ah[2][4], bh4[4][4], bl4[4][4];
            ldm_x4(ah[0], baseAh + ks * 32);
            ldm_x4(ah[1], baseAh + ks * 32 + 1280);
            ldm_x4(bh4[0], baseBh + ks * 32);          // j tiles 0,1
            ldm_x4(bh4[2], baseBh + ks * 32 + 1280);   // j tiles 2,3
            ldm_x4(bl4[0], baseBl + ks * 32);
            ldm_x4(bl4[2], baseBl + ks * 32 + 1280);
            uint32_t bfh[4][2], bfl[4][2];
#pragma unroll
            for (int j = 0; j < 4; j++) {
                bfh[j][0] = bh4[(j >> 1) * 2][(j & 1) * 2 + 0];
                bfh[j][1] = bh4[(j >> 1) * 2][(j & 1) * 2 + 1];
                bfl[j][0] = bl4[(j >> 1) * 2][(j & 1) * 2 + 0];
                bfl[j][1] = bl4[(j >> 1) * 2][(j & 1) * 2 + 1];
            }
#pragma unroll
            for (int i = 0; i < 2; i++)
#pragma unroll
                for (int j = 0; j < 4; j++)
                    mma_f16(c[i][j], ah[i], bfh[j]);
#pragma unroll
            for (int i = 0; i < 2; i++)
#pragma unroll
                for (int j = 0; j < 4; j++)
                    mma_f16(c[i][j], ah[i], bfl[j]);
        }
        __syncthreads();
    }

    // ---------------- epilogues ----------------
#pragma unroll
    for (int i = 0; i < 2; i++) {
#pragma unroll
        for (int j = 0; j < 4; j++) {
#pragma unroll
            for (int r = 0; r < 4; r++) {
                int mm = warp_m * 32 + i * 16 + (lane >> 2) + ((r & 2) ? 8 : 0);
                int nn = warp_n * 32 + j * 8 + (lane & 3) * 2 + (r & 1);
                float v = c[i][j][r];
                if (MODE == MODE_PROJ) {
                    int m = m0 + mm;
                    int n = n0 + nn;
                    int hh = m >> 5, d = m & 31;
                    float* dstp = (which == 0) ? g_q : ((which == 1) ? g_k : g_v);
                    dstp[((size_t)(bb * 8 + hh) * Npix + n) * 32 + d] = v;
                } else {
                    int m = m0 + mm;
                    int n = n0 + nn;
                    dst[((size_t)bb * 256 + m) * 4096 + n] = v;
                }
            }
        }
    }
}

// ---------------- conv kernel: window-reuse implicit GEMM (3-product) --------
// smem: IMGH 0..17920, IMGL 17920..35840, WH [2][64][40] @35840, WL @46080.
#define CV_SMEM 56320

__global__ __launch_bounds__(256) void conv_tc_kernel(const float* __restrict__ bias) {
    extern __shared__ __align__(16) char smem[];
    const uint32_t smb = smem_u32(smem);
    uint32_t* Ih = (uint32_t*)smem;                 // [16][280]
    uint32_t* Il = (uint32_t*)(smem + 17920);

    const int t = threadIdx.x;
    const int lane = t & 31, wid = t >> 5;
    const int warp_m = wid & 1;        // 2 x 32 oc
    const int warp_n = wid >> 1;       // 4 x 32 pix
    const int tile = blockIdx.x;
    const int bb = blockIdx.y;
    const int p0 = tile * 128;
    const int py0 = tile * 2;

    float c[2][4][4];
#pragma unroll
    for (int i = 0; i < 2; i++)
#pragma unroll
        for (int j = 0; j < 4; j++)
#pragma unroll
            for (int r = 0; r < 4; r++) c[i][j][r] = 0.f;

    auto stage_w = [&](int g, int wb) {
        int cblk = g / 9, tap = g - cblk * 9;
        int oc = t >> 2, q = t & 3;
        size_t src = ((size_t)(tap * 64 + oc)) * 256 + cblk * 32 + q * 8;
        uint32_t dsth = smb + 35840 + (wb * 2560 + oc * 40 + q * 8) * 2;
        CP16(dsth, g_wch + src);
        CP16(dsth + 10240, g_wcl + src);
    };

    stage_w(0, 0);
    CP_COMMIT();

    const uint32_t aAddr = ((warp_m * 32 + (lane & 15)) * 40 + ((lane >> 4) * 8)) * 2;
    const int kq = lane & 3;

    for (int cblk = 0; cblk < 8; cblk++) {
        __syncthreads();
        for (int i = t; i < 1088; i += 256) {
            int rl = i / 17, xq = i - rl * 17;
            int c2 = rl >> 2, r = rl & 3;
            size_t src = (((size_t)(bb * 128 + cblk * 16 + c2)) * 66 + (py0 + r)) * 68 + xq * 4;
            int dstw = c2 * 280 + r * 68 + xq * 4;
            *(uint4*)(Ih + dstw) = *(const uint4*)(g_i2h + src);
            *(uint4*)(Il + dstw) = *(const uint4*)(g_i2l + src);
        }
        __syncthreads();

        for (int tap = 0; tap < 9; tap++) {
            const int g = cblk * 9 + tap;
            const int wb = g & 1;
            CP_WAIT0();
            __syncthreads();
            if (g + 1 < 72) { stage_w(g + 1, wb ^ 1); CP_COMMIT(); }

            const int rowoff = tap / 3;
            const int xoff = tap - rowoff * 3;
            const uint32_t baseWh = smb + 35840 + wb * 5120 + aAddr;
            const uint32_t baseWl = smb + 46080 + wb * 5120 + aAddr;

#pragma unroll
            for (int ks = 0; ks < 2; ks++) {
                uint32_t ah[2][4], al[2][4], bh4[4][2], bl4[4][2];
                ldm_x4(ah[0], baseWh + ks * 32);
                ldm_x4(ah[1], baseWh + ks * 32 + 1280);
                ldm_x4(al[0], baseWl + ks * 32);
                ldm_x4(al[1], baseWl + ks * 32 + 1280);
                const int c2b = ks * 8 + kq;
#pragma unroll
                for (int j = 0; j < 4; j++) {
                    int n = warp_n * 32 + j * 8 + (lane >> 2);
                    int addr = c2b * 280 + ((n >> 6) + rowoff) * 68 + (n & 63) + xoff;
                    bh4[j][0] = Ih[addr];
                    bh4[j][1] = Ih[addr + 4 * 280];
                    bl4[j][0] = Il[addr];
                    bl4[j][1] = Il[addr + 4 * 280];
                }
#pragma unroll
                for (int i = 0; i < 2; i++)
#pragma unroll
                    for (int j = 0; j < 4; j++)
                        mma_f16(c[i][j], ah[i], bh4[j]);
#pragma unroll
                for (int i = 0; i < 2; i++)
#pragma unroll
                    for (int j = 0; j < 4; j++)
                        mma_f16(c[i][j], ah[i], bl4[j]);
#pragma unroll
                for (int i = 0; i < 2; i++)
#pragma unroll
                    for (int j = 0; j < 4; j++)
                        mma_f16(c[i][j], al[i], bh4[j]);
            }
        }
    }

    // ---------------- epilogue: bias + tanh + base grid -> g_grids ----------
#pragma unroll
    for (int i = 0; i < 2; i++) {
#pragma unroll
        for (int j = 0; j < 4; j++) {
#pragma unroll
            for (int r = 0; r < 4; r++) {
                int oc = warp_m * 32 + i * 16 + (lane >> 2) + ((r & 2) ? 8 : 0);
                int nn = warp_n * 32 + j * 8 + (lane & 3) * 2 + (r & 1);
                int pix = p0 + nn;
                float w = tanhf(c[i][j][r] + __ldg(&bias[oc])) * 0.25f;
                int comp = oc & 1;
                int hh = oc >> 3, p = (oc >> 1) & 3;
                int py = pix >> 6, px = pix & 63;
                float base = comp ? (py * (2.f / 63.f) - 1.f)
                                  : (px * (2.f / 63.f) - 1.f);
                g_grids[((((size_t)(bb * 8 + hh) * 4 + p) * 4096) + pix) * 2 + comp]
                    = w + base;
            }
        }
    }
}

// ----------------------------------------------------------------------------
// Fused bilinear sampling + attention; emits split-fp16 for the OUT GEMM.
// ----------------------------------------------------------------------------
__global__ __launch_bounds__(256) void attn_kernel()
{
    int gw   = blockIdx.x * 8 + (threadIdx.x >> 5);
    int lane = threadIdx.x & 31;
    int n    = gw >> 12;
    int pix  = gw & 4095;
    int b    = n >> 3;
    int hh   = n & 7;

    float qv = g_q[((size_t)n * 4096 + pix) * 32 + lane];
    const float* kb = g_k + (size_t)n * 1024 * 32;
    const float* vb = g_v + (size_t)n * 1024 * 32;
    const float2* gp = (const float2*)g_grids + (size_t)n * 4 * 4096 + pix;

    float logit[4], vs[4];
#pragma unroll
    for (int p = 0; p < 4; p++) {
        float2 g = gp[(size_t)p * 4096];
        float x = (g.x + 1.f) * 16.f - 0.5f;
        float y = (g.y + 1.f) * 16.f - 0.5f;
        float x0f = floorf(x), y0f = floorf(y);
        float wx1 = x - x0f, wy1 = y - y0f;
        int x0 = (int)x0f, y0 = (int)y0f;
        float ks = 0.f, vv = 0.f;
#pragma unroll
        for (int dy = 0; dy < 2; dy++) {
#pragma unroll
            for (int dx = 0; dx < 2; dx++) {
                int xi = x0 + dx, yi = y0 + dy;
                float w = (dx ? wx1 : 1.f - wx1) * (dy ? wy1 : 1.f - wy1);
                if ((unsigned)xi < 32u && (unsigned)yi < 32u) {
                    int off = ((yi << 5) + xi) << 5;
                    ks = fmaf(w, kb[off + lane], ks);
                    vv = fmaf(w, vb[off + lane], vv);
                }
            }
        }
        float tsum = qv * ks;
#pragma unroll
        for (int o = 16; o > 0; o >>= 1)
            tsum += __shfl_xor_sync(0xffffffffu, tsum, o);
        logit[p] = tsum * 0.17677669529663687f;
        vs[p] = vv;
    }

    float mx = fmaxf(fmaxf(logit[0], logit[1]), fmaxf(logit[2], logit[3]));
    float e0 = expf(logit[0] - mx);
    float e1 = expf(logit[1] - mx);
    float e2 = expf(logit[2] - mx);
    float e3 = expf(logit[3] - mx);
    float inv = 1.f / (e0 + e1 + e2 + e3);
    float o = (e0 * vs[0] + e1 * vs[1] + e2 * vs[2] + e3 * vs[3]) * inv;

    uint16_t h, l;
    split_f16(o, h, l);
    size_t idx = ((size_t)b * 4096 + pix) * 256 + hh * 32 + lane;
    g_attnh[idx] = h;
    g_attnl[idx] = l;
}

// ----------------------------------------------------------------------------
extern "C" void kernel_launch(void* const* d_in, const int* in_sizes, int n_in,
                              void* d_out, int out_size)
{
    (void)in_sizes; (void)n_in; (void)out_size;
    const float* query = (const float*)d_in[0];
    const float* kv    = (const float*)d_in[1];
    const float* q_w   = (const float*)d_in[2];
    const float* k_w   = (const float*)d_in[3];
    const float* v_w   = (const float*)d_in[4];
    const float* off_w = (const float*)d_in[5];
    const float* off_b = (const float*)d_in[6];
    const float* out_w = (const float*)d_in[7];
    float* out = (float*)d_out;

    cudaFuncSetAttribute(mma_gemm<MODE_PROJ>,
                         cudaFuncAttributeMaxDynamicSharedMemorySize, PJ_SMEM);
    cudaFuncSetAttribute(mma_gemm<MODE_OUT>,
                         cudaFuncAttributeMaxDynamicSharedMemorySize, PJ_SMEM);
    cudaFuncSetAttribute(conv_tc_kernel,
                         cudaFuncAttributeMaxDynamicSharedMemorySize, CV_SMEM);

    uint16_t *xqh, *xql, *xkh, *xkl, *ath, *atl, *pwh;
    cudaGetSymbolAddress((void**)&xqh, g_xqh);
    cudaGetSymbolAddress((void**)&xql, g_xql);
    cudaGetSymbolAddress((void**)&xkh, g_xkh);
    cudaGetSymbolAddress((void**)&xkl, g_xkl);
    cudaGetSymbolAddress((void**)&ath, g_attnh);
    cudaGetSymbolAddress((void**)&atl, g_attnl);
    cudaGetSymbolAddress((void**)&pwh, g_pwh);

    // launches 0-3
    prep_img2_kernel<<<(8 * 128 * 66 * 68 + 255) / 256, 256>>>(query);
    prep_w_kernel<<<(9 * 64 * 256 + 255) / 256, 256>>>(off_w);
    prep_pw_kernel<<<dim3(256, 4), 256>>>(q_w, k_w, v_w, out_w);
    tsplit_kernel<<<dim3(4096 / 32, 8, 8), 256>>>(query, xqh, xql, 4096);

    // launch 4 (ncu capture slot): offset conv -> grids
    conv_tc_kernel<<<dim3(32, 8), 256, CV_SMEM>>>(off_b);

    tsplit_kernel<<<dim3(1024 / 32, 8, 8), 256>>>(kv, xkh, xkl, 1024);

    // projections
    mma_gemm<MODE_PROJ><<<dim3(64, 2, 8), 256, PJ_SMEM>>>(
        pwh + 0 * 65536, xqh, xql, nullptr, 4096, 0);
    mma_gemm<MODE_PROJ><<<dim3(16, 2, 8), 256, PJ_SMEM>>>(
        pwh + 1 * 65536, xkh, xkl, nullptr, 1024, 1);
    mma_gemm<MODE_PROJ><<<dim3(16, 2, 8), 256, PJ_SMEM>>>(
        pwh + 2 * 65536, xkh, xkl, nullptr, 1024, 2);

    // fused bilinear sample + attention -> split attn
    attn_kernel<<<(64 * 4096) / 8, 256>>>();

    // output projection -> d_out
    mma_gemm<MODE_OUT><<<dim3(64, 2, 8), 256, PJ_SMEM>>>(
        pwh + 3 * 65536, ath, atl, out, 4096, 0);
}